// round 10
// baseline (speedup 1.0000x reference)
#include <cuda_runtime.h>
#include <math.h>

#define NPROB 4096
#define TPB   256
#define ITERS 80
static constexpr float SIGMA_  = 1e-6f;
static constexpr float EPSLMO_ = 1e-4f;

__device__ float g_xfeas[NPROB * 64];

#define FMA2(d,a,b)  asm("fma.rn.f32x2 %0, %1, %2, %0;" : "+l"(d) : "l"(a), "l"(b))
#define PACK2(d,x,y) asm("mov.b64 %0, {%1, %2};" : "=l"(d) : "f"(x), "f"(y))
#define UNPK2(x,y,v) asm("mov.b64 {%0, %1}, %2;" : "=f"(x), "=f"(y) : "l"(v))

__device__ __forceinline__ float dot4(float4 a, float4 b){
    return a.x*b.x + a.y*b.y + a.z*b.z + a.w*b.w;
}
__device__ __forceinline__ float dotA(const float* sA, int i, const float* v){
    const float4* a4 = (const float4*)(sA + i*68);
    const float4* v4 = (const float4*)v;
    float s = 0.f;
#pragma unroll
    for (int q = 0; q < 16; ++q) s += dot4(a4[q], v4[q]);
    return s;
}

// ---------------------------------------------------------------------------
// Register-resident GJ inverse of M = diag*I + A^T A (64x64), result -> sM.
// Thread t: row gi = t&63, cols [j0, j0+16), j0 = (t>>6)*16, in R[16].
// ---------------------------------------------------------------------------
__device__ __forceinline__ void gj64_reg(const float* sA, float* sM, float diag,
                                         float* bufRow, float* bufCol, float* bufPinv)
{
    const int t  = threadIdx.x;
    const int gi = t & 63;
    const int cb = t >> 6;
    const int j0 = cb << 4;

    float R[16];
#pragma unroll
    for (int l = 0; l < 16; ++l) R[l] = 0.f;
    for (int r = 0; r < 32; ++r){
        float  ag = sA[r*68 + gi];
        float4 a0 = *(const float4*)(sA + r*68 + j0);
        float4 a1 = *(const float4*)(sA + r*68 + j0 + 4);
        float4 a2 = *(const float4*)(sA + r*68 + j0 + 8);
        float4 a3 = *(const float4*)(sA + r*68 + j0 + 12);
        R[0]+=ag*a0.x; R[1]+=ag*a0.y; R[2]+=ag*a0.z; R[3]+=ag*a0.w;
        R[4]+=ag*a1.x; R[5]+=ag*a1.y; R[6]+=ag*a1.z; R[7]+=ag*a1.w;
        R[8]+=ag*a2.x; R[9]+=ag*a2.y; R[10]+=ag*a2.z; R[11]+=ag*a2.w;
        R[12]+=ag*a3.x; R[13]+=ag*a3.y; R[14]+=ag*a3.z; R[15]+=ag*a3.w;
    }
    if ((gi >> 4) == cb){
#pragma unroll
        for (int l = 0; l < 16; ++l) if ((gi & 15) == l) R[l] += diag;
    }
    if (gi == 0){
        *(float4*)(bufRow + j0)      = make_float4(R[0],R[1],R[2],R[3]);
        *(float4*)(bufRow + j0 + 4)  = make_float4(R[4],R[5],R[6],R[7]);
        *(float4*)(bufRow + j0 + 8)  = make_float4(R[8],R[9],R[10],R[11]);
        *(float4*)(bufRow + j0 + 12) = make_float4(R[12],R[13],R[14],R[15]);
        if (cb == 0) bufPinv[0] = __frcp_rn(R[0]);
    }
    if (cb == 0) bufCol[gi] = R[0];
    __syncthreads();

    for (int ko = 0; ko < 4; ++ko){
#pragma unroll
        for (int ki = 0; ki < 16; ++ki){
            const int k = ko*16 + ki;
            const int b = ki & 1;
            float pinv = bufPinv[b];
            float pc   = bufCol[b*64 + gi];
            const bool isk = (gi == k);
            float fac = isk ? pinv : (-pc * pinv);
#pragma unroll
            for (int q = 0; q < 4; ++q){
                float4 p = *(const float4*)(bufRow + b*64 + j0 + 4*q);
                if (isk){
                    R[4*q+0] = p.x*fac; R[4*q+1] = p.y*fac;
                    R[4*q+2] = p.z*fac; R[4*q+3] = p.w*fac;
                } else {
                    R[4*q+0] += p.x*fac; R[4*q+1] += p.y*fac;
                    R[4*q+2] += p.z*fac; R[4*q+3] += p.w*fac;
                }
            }
            if (ko == cb) R[ki] = isk ? pinv : fac;
            if (k < 63){
                const int kn  = k + 1;
                const int bn  = kn & 1;
                const int kol = (ki == 15) ? (ko + 1) : ko;
                const int lnl = (ki + 1) & 15;
                if (gi == kn){
                    *(float4*)(bufRow + bn*64 + j0)      = make_float4(R[0],R[1],R[2],R[3]);
                    *(float4*)(bufRow + bn*64 + j0 + 4)  = make_float4(R[4],R[5],R[6],R[7]);
                    *(float4*)(bufRow + bn*64 + j0 + 8)  = make_float4(R[8],R[9],R[10],R[11]);
                    *(float4*)(bufRow + bn*64 + j0 + 12) = make_float4(R[12],R[13],R[14],R[15]);
                    if (kol == cb) bufPinv[bn] = __frcp_rn(R[lnl]);
                }
                if (kol == cb) bufCol[bn*64 + gi] = R[lnl];
            }
            __syncthreads();
        }
    }
    *(float4*)(sM + gi*68 + j0)      = make_float4(R[0],R[1],R[2],R[3]);
    *(float4*)(sM + gi*68 + j0 + 4)  = make_float4(R[4],R[5],R[6],R[7]);
    *(float4*)(sM + gi*68 + j0 + 8)  = make_float4(R[8],R[9],R[10],R[11]);
    *(float4*)(sM + gi*68 + j0 + 12) = make_float4(R[12],R[13],R[14],R[15]);
    __syncthreads();
}

// T (64x32, stride 36) = N * A^T
__device__ __forceinline__ void gemmT(const float* sM, const float* sA, float* sT)
{
    const int t  = threadIdx.x;
    const int i0 = (t >> 4) << 2;
    const int r0 = (t & 15) << 1;
    float acc[4][2] = {};
    for (int j = 0; j < 64; j += 4){
        float4 a0 = *(const float4*)(sA + r0*68     + j);
        float4 a1 = *(const float4*)(sA + (r0+1)*68 + j);
#pragma unroll
        for (int a = 0; a < 4; ++a){
            float4 nv = *(const float4*)(sM + (i0+a)*68 + j);
            acc[a][0] += dot4(nv, a0);
            acc[a][1] += dot4(nv, a1);
        }
    }
#pragma unroll
    for (int a = 0; a < 4; ++a){
        sT[(i0+a)*36 + r0]     = acc[a][0];
        sT[(i0+a)*36 + r0 + 1] = acc[a][1];
    }
}

// S (32x32, stride 36) = A * T  (A operand loaded as broadcast float4)
__device__ __forceinline__ void gemmS(const float* sA, const float* sT, float* sS)
{
    const int t  = threadIdx.x;
    const int r  = t >> 3;
    const int cb = (t & 7) << 2;
    float4 acc = make_float4(0.f,0.f,0.f,0.f);
#pragma unroll
    for (int i4 = 0; i4 < 16; ++i4){
        float4 av = *(const float4*)(sA + r*68 + 4*i4);
        float4 t0 = *(const float4*)(sT + (4*i4+0)*36 + cb);
        float4 t1 = *(const float4*)(sT + (4*i4+1)*36 + cb);
        float4 t2 = *(const float4*)(sT + (4*i4+2)*36 + cb);
        float4 t3 = *(const float4*)(sT + (4*i4+3)*36 + cb);
        acc.x += av.x*t0.x + av.y*t1.x + av.z*t2.x + av.w*t3.x;
        acc.y += av.x*t0.y + av.y*t1.y + av.z*t2.y + av.w*t3.y;
        acc.z += av.x*t0.z + av.y*t1.z + av.z*t2.z + av.w*t3.z;
        acc.w += av.x*t0.w + av.y*t1.w + av.z*t2.w + av.w*t3.w;
    }
    *(float4*)(sS + r*36 + cb) = acc;
}

// ======================= ANCHOR: d=68 (Schur), K=100 (pad 104) ==============
__device__ __forceinline__ float gA(int r, int c, const float* sM, const float* sT,
                                    const float* sS, const float* sW, const float* sV,
                                    const float* sXi)
{
    if (c >= 100) return 0.f;
    if (r < 64){
        if (c < 64) return sM[r*68 + c];
        if (c < 92) return sT[r*36 + (c-64)];
        if (c < 96) return sT[r*36 + 28 + (c-92)] + sW[r*4 + (c-92)];
        return -sW[r*4 + (c-96)];
    }
    if (r < 92){ int i = r-64;
        if (c < 64) return sT[c*36 + i];
        if (c < 92) return sS[i*36 + (c-64)];
        if (c < 96) return sS[i*36 + 28 + (c-92)] + sV[i*4 + (c-92)];
        return -sV[i*4 + (c-96)];
    }
    if (r < 96){ int m = r-92, i = 28+m;
        if (c < 64) return sT[c*36 + i] + sW[c*4 + m];
        if (c < 92) return sS[i*36 + (c-64)] + sV[(c-64)*4 + m];
        if (c < 96){ int j = c-92;
            return sS[i*36 + 28 + j] + sV[i*4 + j] + sV[(28+j)*4 + m] + sXi[m*4 + j]; }
        { int j = c-96; return -sV[i*4 + j] - sXi[m*4 + j]; }
    }
    { int m = r-96;
        if (c < 64) return -sW[c*4 + m];
        if (c < 92) return -sV[(c-64)*4 + m];
        if (c < 96){ int j = c-92; return -sV[(28+j)*4 + m] - sXi[m*4 + j]; }
        { int j = c-96; return sXi[m*4 + j]; }
    }
}

__global__ void __launch_bounds__(TPB, 4)
anchor_kernel(const float* __restrict__ xr, const float* __restrict__ Ain,
              const float* __restrict__ bin)
{
    extern __shared__ float sm[];
    float* sA  = sm;             // 32*68
    float* sM  = sA  + 2176;     // 64*68
    float* sT  = sM  + 4352;     // 64*36
    float* sS  = sT  + 2304;     // 32*36
    float* sY  = sS  + 1152;     // 64*4
    float* sW  = sY  + 256;      // 64*4
    float* sU  = sW  + 256;      // 32*4
    float* sV  = sU  + 128;      // 32*4
    float* sXi = sV  + 128;      // 16
    float* sv  = sXi + 16;       // 2*104
    float* su0 = sv  + 208;      // 68
    float* sdx = su0 + 68;       // 68
    float* sxr = sdx + 68;       // 64
    float* bR  = sxr + 64;       // 128
    float* bC  = bR  + 128;      // 128
    float* bP  = bC  + 128;      // 2 + pad

    const int p = blockIdx.x;
    const int t = threadIdx.x;
    const float* Ap = Ain + (size_t)p * 2048;
    const float* bp = bin + (size_t)p * 32;

    for (int e = t; e < 2048; e += TPB) sA[(e>>6)*68 + (e&63)] = Ap[e];
    if (t < 64) sxr[t] = xr[(size_t)p*64 + t];
    if (t >= 64 && t < 72){ int q = t-64; sv[100 + (q&3) + (q>>2)*104] = 0.f; }
    __syncthreads();

    gj64_reg(sA, sM, 2.0f + SIGMA_, bR, bC, bP);
    gemmT(sM, sA, sT);
    __syncthreads();
    gemmS(sA, sT, sS);
    __syncthreads();

    if (t == 0){
        float X[4][4];
        for (int m = 0; m < 4; ++m)
            for (int j = 0; j < 4; ++j)
                X[m][j] = ((m==j) ? (4.0f+SIGMA_) : 0.f) - sS[(28+m)*36 + 28 + j];
        for (int k = 0; k < 4; ++k){
            float pinv = 1.0f / X[k][k];
            for (int j = 0; j < 4; ++j) if (j != k) X[k][j] *= pinv;
            X[k][k] = pinv;
            for (int i = 0; i < 4; ++i) if (i != k){
                float f = X[i][k];
                for (int j = 0; j < 4; ++j) if (j != k) X[i][j] -= f * X[k][j];
                X[i][k] = -f * pinv;
            }
        }
        for (int m = 0; m < 4; ++m)
            for (int j = 0; j < 4; ++j) sXi[m*4+j] = X[m][j];
    }
    __syncthreads();
    if (t < 64){
        float y[4];
#pragma unroll
        for (int m = 0; m < 4; ++m){ y[m] = -sT[t*36 + 28 + m]; sY[t*4+m] = y[m]; }
#pragma unroll
        for (int m = 0; m < 4; ++m){
            float a = 0.f;
#pragma unroll
            for (int j = 0; j < 4; ++j) a += y[j] * sXi[j*4+m];
            sW[t*4+m] = a;
        }
    } else if (t < 96){
        int r = t - 64;
        float u[4];
#pragma unroll
        for (int m = 0; m < 4; ++m){ u[m] = -sS[r*36 + 28 + m]; sU[r*4+m] = u[m]; }
#pragma unroll
        for (int m = 0; m < 4; ++m){
            float a = 0.f;
#pragma unroll
            for (int j = 0; j < 4; ++j) a += u[j] * sXi[j*4+m];
            sV[r*4+m] = a;
        }
    }
    __syncthreads();
    for (int e = t; e < 4096; e += TPB){
        int i = e >> 6, j = e & 63; float a = 0.f;
#pragma unroll
        for (int m = 0; m < 4; ++m) a += sW[i*4+m] * sY[j*4+m];
        sM[i*68 + j] += a;
    }
    for (int e = t; e < 2048; e += TPB){
        int i = e >> 5, a0 = e & 31; float a = 0.f;
#pragma unroll
        for (int m = 0; m < 4; ++m) a += sW[i*4+m] * sU[a0*4+m];
        sT[i*36 + a0] += a;
    }
    for (int e = t; e < 1024; e += TPB){
        int r = e >> 5, c = e & 31; float a = 0.f;
#pragma unroll
        for (int m = 0; m < 4; ++m) a += sV[r*4+m] * sU[c*4+m];
        sS[r*36 + c] += a;
    }
    __syncthreads();
    if (t < 64) su0[t] = dotA(sM, t, sxr);
    else if (t < 68){
        int m = t - 64; float a = 0.f;
        for (int j = 0; j < 64; ++j) a -= sW[j*4+m] * sxr[j];
        su0[64+m] = a;
    }
    __syncthreads();

    const int row = t >> 1, h = t & 1;
    float lo = 0.f, hi = 0.f, cx0 = 0.f;
    if (t < 200){
        if (row < 64){ lo = 0.f; hi = INFINITY; cx0 = su0[row]; }
        else if (row < 92){ int i = row-64; lo = -INFINITY; hi = bp[i]; cx0 = dotA(sA, i, su0); }
        else if (row < 96){ int m = row-92; int i = 28+m;
            lo = -INFINITY; hi = bp[i]; cx0 = dotA(sA, i, su0) - su0[64+m]; }
        else { int m = row-96; lo = 0.f; hi = INFINITY; cx0 = su0[64+m]; }
    }
    unsigned long long G2[26];
    if (t < 200){
#pragma unroll
        for (int c2 = 0; c2 < 26; ++c2){
            float g0 = gA(row, h*52 + 2*c2,     sM, sT, sS, sW, sV, sXi);
            float g1 = gA(row, h*52 + 2*c2 + 1, sM, sT, sS, sW, sV, sXi);
            PACK2(G2[c2], g0, g1);
        }
    }
    __syncthreads();

    float z = fminf(fmaxf(0.f, lo), hi), y = 0.f;
    for (int it = 0; it < ITERS; ++it){
        float* vb = sv + (it & 1) * 104;
        if (t < 200 && h == 0) vb[row] = z - y;
        __syncthreads();
        const ulonglong2* v2 = (const ulonglong2*)vb + h*13;
        unsigned long long a0 = 0ull, a1 = 0ull, a2 = 0ull, a3 = 0ull;
#pragma unroll
        for (int c = 0; c < 13; ++c){
            ulonglong2 vv = v2[c];
            if (c & 1){ FMA2(a2, G2[2*c], vv.x); FMA2(a3, G2[2*c+1], vv.y); }
            else      { FMA2(a0, G2[2*c], vv.x); FMA2(a1, G2[2*c+1], vv.y); }
        }
        float x0, x1, x2, x3, x4, x5, x6, x7;
        UNPK2(x0, x1, a0); UNPK2(x2, x3, a1); UNPK2(x4, x5, a2); UNPK2(x6, x7, a3);
        float acc = ((x0+x1)+(x2+x3)) + ((x4+x5)+(x6+x7));
        acc += __shfl_xor_sync(0xFFFFFFFFu, acc, 1);
        float Cx = cx0 + acc;
        float zn = fminf(fmaxf(Cx + y, lo), hi);
        y += Cx - zn; z = zn;
    }
    __syncthreads();

    const float* vl = sv + ((ITERS-1) & 1) * 104;
    if (t < 64){
        float a = vl[t];
        for (int r = 0; r < 28; ++r) a += sA[r*68 + t] * vl[64+r];
#pragma unroll
        for (int r = 28; r < 32; ++r) a += sA[r*68 + t] * vl[92 + (r-28)];
        sdx[t] = a;
    } else if (t < 68){
        int m = t - 64; sdx[64+m] = vl[96+m] - vl[92+m];
    }
    __syncthreads();
    if (t < 64){
        float a = su0[t] + dotA(sM, t, sdx);
#pragma unroll
        for (int m = 0; m < 4; ++m) a -= sW[t*4+m] * sdx[64+m];
        g_xfeas[(size_t)p*64 + t] = a;
    }
}

// ======================= LMO: d=64, K=96 ====================================
__global__ void __launch_bounds__(TPB, 4)
lmo_kernel(const float* __restrict__ Ain, const float* __restrict__ bin,
           const float* __restrict__ W1, const float* __restrict__ w2,
           float* __restrict__ out)
{
    extern __shared__ float sm[];
    float* sA  = sm;             // 32*68 (normalized)
    float* sM  = sA  + 2176;     // 64*68
    float* sT  = sM  + 4352;     // 64*36
    float* sS  = sT  + 2304;     // 32*36
    float* sv  = sS  + 1152;     // 2*96
    float* su0 = sv  + 192;      // 64
    float* sd  = su0 + 64;       // 64
    float* sx  = sd  + 64;       // 64
    float* shb = sx  + 64;       // 256
    float* sg  = shb + 256;      // 64
    float* srv = sg  + 64;       // 32
    float* bR  = srv + 32;       // 128
    float* bC  = bR  + 128;      // 128
    float* bP  = bC  + 128;      // 2 + pad

    const int p = blockIdx.x;
    const int t = threadIdx.x;
    const float* Ap = Ain + (size_t)p * 2048;
    const float* bp = bin + (size_t)p * 32;

    for (int e = t; e < 2048; e += TPB) sA[(e>>6)*68 + (e&63)] = Ap[e];
    if (t < 64) sx[t] = g_xfeas[(size_t)p*64 + t];
    __syncthreads();

    if (t < 32){
        float ss = 0.f;
        const float* Ar = sA + t*68;
        for (int i = 0; i < 64; ++i) ss += Ar[i]*Ar[i];
        srv[t] = 1.0f / fmaxf(sqrtf(ss), 1e-12f);
    }
    {
        float a = 0.f;
        for (int i = 0; i < 64; ++i) a += sx[i] * W1[i*256 + t];
        float hh = tanhf(a);
        shb[t] = (1.f - hh*hh) * w2[t];
    }
    __syncthreads();
    for (int e = t; e < 2048; e += TPB){
        int r = e >> 6;
        sA[r*68 + (e&63)] *= srv[r];
    }
    {
        int wid = t >> 5, lane = t & 31;
        for (int rr = 0; rr < 8; ++rr){
            int i = wid*8 + rr;
            const float* Wr = W1 + i*256;
            float a = 0.f;
#pragma unroll
            for (int k = 0; k < 8; ++k) a += Wr[k*32 + lane] * shb[k*32 + lane];
#pragma unroll
            for (int o = 16; o; o >>= 1) a += __shfl_xor_sync(0xFFFFFFFFu, a, o);
            if (lane == 0) sg[i] = a;
        }
    }
    __syncthreads();

    gj64_reg(sA, sM, 1.0f + EPSLMO_ + SIGMA_, bR, bC, bP);
    gemmT(sM, sA, sT);
    __syncthreads();
    gemmS(sA, sT, sS);
    if (t < 64) su0[t] = dotA(sM, t, sg);
    __syncthreads();

    const int row = t >> 1, h = t & 1;
    float lo = 0.f, hi = 0.f, cx0 = 0.f;
    if (t < 192){
        if (row < 64){ lo = 0.f; hi = INFINITY; cx0 = su0[row]; }
        else { int a = row - 64; lo = -INFINITY; hi = bp[a] * srv[a]; cx0 = dotA(sA, a, su0); }
    }
    unsigned long long G2[24];
    if (t < 192){
#pragma unroll
        for (int c2 = 0; c2 < 24; ++c2){
            int c0 = h*48 + 2*c2, c1 = c0 + 1;
            float g0, g1;
            if (row < 64){
                g0 = (c0 < 64) ? sM[row*68 + c0] : sT[row*36 + (c0-64)];
                g1 = (c1 < 64) ? sM[row*68 + c1] : sT[row*36 + (c1-64)];
            } else {
                int a = row - 64;
                g0 = (c0 < 64) ? sT[c0*36 + a] : sS[a*36 + (c0-64)];
                g1 = (c1 < 64) ? sT[c1*36 + a] : sS[a*36 + (c1-64)];
            }
            PACK2(G2[c2], g0, g1);
        }
    }
    __syncthreads();

    float z = fminf(fmaxf(0.f, lo), hi), y = 0.f;
    for (int it = 0; it < ITERS; ++it){
        float* vb = sv + (it & 1) * 96;
        if (t < 192 && h == 0) vb[row] = z - y;
        __syncthreads();
        const ulonglong2* v2 = (const ulonglong2*)vb + h*12;
        unsigned long long a0 = 0ull, a1 = 0ull, a2 = 0ull, a3 = 0ull;
#pragma unroll
        for (int c = 0; c < 12; ++c){
            ulonglong2 vv = v2[c];
            if (c & 1){ FMA2(a2, G2[2*c], vv.x); FMA2(a3, G2[2*c+1], vv.y); }
            else      { FMA2(a0, G2[2*c], vv.x); FMA2(a1, G2[2*c+1], vv.y); }
        }
        float x0, x1, x2, x3, x4, x5, x6, x7;
        UNPK2(x0, x1, a0); UNPK2(x2, x3, a1); UNPK2(x4, x5, a2); UNPK2(x6, x7, a3);
        float acc = ((x0+x1)+(x2+x3)) + ((x4+x5)+(x6+x7));
        acc += __shfl_xor_sync(0xFFFFFFFFu, acc, 1);
        float Cx = cx0 + acc;
        float zn = fminf(fmaxf(Cx + y, lo), hi);
        y += Cx - zn; z = zn;
    }
    __syncthreads();

    const float* vl = sv + ((ITERS-1) & 1) * 96;
    if (t < 64){
        float a = vl[t];
        for (int r = 0; r < 32; ++r) a += sA[r*68 + t] * vl[64+r];
        sd[t] = a;
    }
    __syncthreads();
    if (t < 64){
        float c_sol = su0[t] + dotA(sM, t, sd);
        out[(size_t)p*64 + t] = 0.9f * sx[t] + 0.1f * c_sol;
    }
}

// ---------------------------------------------------------------------------
extern "C" void kernel_launch(void* const* d_in, const int* in_sizes, int n_in,
                              void* d_out, int out_size)
{
    const float* xr = (const float*)d_in[0];
    const float* A  = (const float*)d_in[1];
    const float* b  = (const float*)d_in[2];
    const float* W1 = (const float*)d_in[3];
    const float* w2 = (const float*)d_in[4];
    float* out = (float*)d_out;

    const int a_smem = (2176 + 4352 + 2304 + 1152 + 256 + 256 + 128 + 128 + 16
                        + 208 + 68 + 68 + 64 + 128 + 128 + 8) * (int)sizeof(float);
    const int l_smem = (2176 + 4352 + 2304 + 1152 + 192 + 64 + 64 + 64 + 256
                        + 64 + 32 + 128 + 128 + 8) * (int)sizeof(float);

    cudaFuncSetAttribute(anchor_kernel, cudaFuncAttributeMaxDynamicSharedMemorySize, a_smem);
    cudaFuncSetAttribute(lmo_kernel,    cudaFuncAttributeMaxDynamicSharedMemorySize, l_smem);

    anchor_kernel<<<NPROB, TPB, a_smem>>>(xr, A, b);
    lmo_kernel<<<NPROB, TPB, l_smem>>>(A, b, W1, w2, out);
}

// round 11
// speedup vs baseline: 1.0294x; 1.0294x over previous
#include <cuda_runtime.h>
#include <math.h>

#define NPROB 4096
#define TPB   256
#define ITERS 80
static constexpr float SIGMA_  = 1e-6f;
static constexpr float EPSLMO_ = 1e-4f;

__device__ float g_xfeas[NPROB * 64];

#define FMA2(d,a,b)  asm("fma.rn.f32x2 %0, %1, %2, %0;" : "+l"(d) : "l"(a), "l"(b))
#define PACK2(d,x,y) asm("mov.b64 %0, {%1, %2};" : "=l"(d) : "f"(x), "f"(y))
#define UNPK2(x,y,v) asm("mov.b64 {%0, %1}, %2;" : "=f"(x), "=f"(y) : "l"(v))

__device__ __forceinline__ float dot4(float4 a, float4 b){
    return a.x*b.x + a.y*b.y + a.z*b.z + a.w*b.w;
}
__device__ __forceinline__ float dotA(const float* sA, int i, const float* v){
    const float4* a4 = (const float4*)(sA + i*68);
    const float4* v4 = (const float4*)v;
    float s = 0.f;
#pragma unroll
    for (int q = 0; q < 16; ++q) s += dot4(a4[q], v4[q]);
    return s;
}

// ---------------------------------------------------------------------------
// Register-resident GJ inverse of M = diag*I + A^T A (64x64) -> sM (stride 68).
// TWO pivots per __syncthreads: pivot rows/cols k and k+1 are published
// together; each thread reconstructs the post-pivot-k row k+1 from broadcast
// data and applies both pivots back-to-back. 32 barriers instead of 64.
// bR1,bR2,bC1,bC2: 2*64 floats each (parity ping-pong).
// ---------------------------------------------------------------------------
__device__ __forceinline__ void gj64_reg2(const float* sA, float* sM, float diag,
                                          float* bR1, float* bR2,
                                          float* bC1, float* bC2)
{
    const int t  = threadIdx.x;
    const int gi = t & 63;
    const int cb = t >> 6;
    const int j0 = cb << 4;

    float R[16];
#pragma unroll
    for (int l = 0; l < 16; ++l) R[l] = 0.f;
    for (int r = 0; r < 32; ++r){
        float  ag = sA[r*68 + gi];
        float4 a0 = *(const float4*)(sA + r*68 + j0);
        float4 a1 = *(const float4*)(sA + r*68 + j0 + 4);
        float4 a2 = *(const float4*)(sA + r*68 + j0 + 8);
        float4 a3 = *(const float4*)(sA + r*68 + j0 + 12);
        R[0]+=ag*a0.x; R[1]+=ag*a0.y; R[2]+=ag*a0.z; R[3]+=ag*a0.w;
        R[4]+=ag*a1.x; R[5]+=ag*a1.y; R[6]+=ag*a1.z; R[7]+=ag*a1.w;
        R[8]+=ag*a2.x; R[9]+=ag*a2.y; R[10]+=ag*a2.z; R[11]+=ag*a2.w;
        R[12]+=ag*a3.x; R[13]+=ag*a3.y; R[14]+=ag*a3.z; R[15]+=ag*a3.w;
    }
    if ((gi >> 4) == cb){
#pragma unroll
        for (int l = 0; l < 16; ++l) if ((gi & 15) == l) R[l] += diag;
    }
    // publish rows 0,1 and cols 0,1 at parity 0
    if (gi == 0){
        *(float4*)(bR1 + j0)      = make_float4(R[0],R[1],R[2],R[3]);
        *(float4*)(bR1 + j0 + 4)  = make_float4(R[4],R[5],R[6],R[7]);
        *(float4*)(bR1 + j0 + 8)  = make_float4(R[8],R[9],R[10],R[11]);
        *(float4*)(bR1 + j0 + 12) = make_float4(R[12],R[13],R[14],R[15]);
    }
    if (gi == 1){
        *(float4*)(bR2 + j0)      = make_float4(R[0],R[1],R[2],R[3]);
        *(float4*)(bR2 + j0 + 4)  = make_float4(R[4],R[5],R[6],R[7]);
        *(float4*)(bR2 + j0 + 8)  = make_float4(R[8],R[9],R[10],R[11]);
        *(float4*)(bR2 + j0 + 12) = make_float4(R[12],R[13],R[14],R[15]);
    }
    if (cb == 0){ bC1[gi] = R[0]; bC2[gi] = R[1]; }
    __syncthreads();

    for (int ko = 0; ko < 4; ++ko){
#pragma unroll
        for (int kh = 0; kh < 8; ++kh){
            const int k1 = ko*16 + kh*2;
            const int pb = ((ko*8 + kh) & 1) << 6;
            const float* r1 = bR1 + pb;
            const float* r2 = bR2 + pb;
            const float* c1 = bC1 + pb;
            const float* c2 = bC2 + pb;

            const bool isk1 = (gi == k1);
            const bool isk2 = (gi == k1 + 1);
            float pinv1 = __frcp_rn(r1[k1]);
            float r1k2  = r1[k1 + 1];
            float fac1  = isk1 ? pinv1 : (-c1[gi] * pinv1);
            float f12   = -c1[k1 + 1] * pinv1;        // pivot1 factor of row k2
            float pinv2 = __frcp_rn(r2[k1 + 1] + f12 * r1k2);
            float c2p   = (isk1 ? 0.f : c2[gi]) + fac1 * r1k2;
            float fac2  = isk2 ? pinv2 : (-c2p * pinv2);

            const int qk = kh >> 1;                   // chunk holding cols k1,k2
            const int i1 = (kh * 2) & 3;              // 0 or 2
#pragma unroll
            for (int q = 0; q < 4; ++q){
                float4 p1 = *(const float4*)(r1 + j0 + 4*q);
                float4 p2 = *(const float4*)(r2 + j0 + 4*q);
                float rr0=R[4*q+0], rr1=R[4*q+1], rr2=R[4*q+2], rr3=R[4*q+3];
                if (isk1){ rr0=p1.x*pinv1; rr1=p1.y*pinv1; rr2=p1.z*pinv1; rr3=p1.w*pinv1; }
                else     { rr0+=fac1*p1.x; rr1+=fac1*p1.y; rr2+=fac1*p1.z; rr3+=fac1*p1.w; }
                float pp0 = p2.x + f12*p1.x, pp1 = p2.y + f12*p1.y;
                float pp2 = p2.z + f12*p1.z, pp3 = p2.w + f12*p1.w;
                if (q == qk && ko == cb){
                    if (i1 == 0){ rr0 = fac1; pp0 = f12; }
                    else        { rr2 = fac1; pp2 = f12; }
                }
                if (isk2){ rr0=pp0*pinv2; rr1=pp1*pinv2; rr2=pp2*pinv2; rr3=pp3*pinv2; }
                else     { rr0+=fac2*pp0; rr1+=fac2*pp1; rr2+=fac2*pp2; rr3+=fac2*pp3; }
                R[4*q+0]=rr0; R[4*q+1]=rr1; R[4*q+2]=rr2; R[4*q+3]=rr3;
            }
            if (ko == cb) R[kh*2 + 1] = fac2;         // inverse-col k2 overwrite

            if (k1 < 62){
                const int kn1 = k1 + 2;
                const int pbn = pb ^ 64;
                if (gi == kn1){
                    *(float4*)(bR1 + pbn + j0)      = make_float4(R[0],R[1],R[2],R[3]);
                    *(float4*)(bR1 + pbn + j0 + 4)  = make_float4(R[4],R[5],R[6],R[7]);
                    *(float4*)(bR1 + pbn + j0 + 8)  = make_float4(R[8],R[9],R[10],R[11]);
                    *(float4*)(bR1 + pbn + j0 + 12) = make_float4(R[12],R[13],R[14],R[15]);
                }
                if (gi == kn1 + 1){
                    *(float4*)(bR2 + pbn + j0)      = make_float4(R[0],R[1],R[2],R[3]);
                    *(float4*)(bR2 + pbn + j0 + 4)  = make_float4(R[4],R[5],R[6],R[7]);
                    *(float4*)(bR2 + pbn + j0 + 8)  = make_float4(R[8],R[9],R[10],R[11]);
                    *(float4*)(bR2 + pbn + j0 + 12) = make_float4(R[12],R[13],R[14],R[15]);
                }
                const int kon = (kh == 7) ? ko + 1 : ko;
                if (kon == cb){
                    bC1[pbn + gi] = R[(kh == 7) ? 0 : (kh*2 + 2)];
                    bC2[pbn + gi] = R[(kh == 7) ? 1 : (kh*2 + 3)];
                }
            }
            __syncthreads();
        }
    }
    *(float4*)(sM + gi*68 + j0)      = make_float4(R[0],R[1],R[2],R[3]);
    *(float4*)(sM + gi*68 + j0 + 4)  = make_float4(R[4],R[5],R[6],R[7]);
    *(float4*)(sM + gi*68 + j0 + 8)  = make_float4(R[8],R[9],R[10],R[11]);
    *(float4*)(sM + gi*68 + j0 + 12) = make_float4(R[12],R[13],R[14],R[15]);
    __syncthreads();
}

// T (64x32, stride 36) = N * A^T
__device__ __forceinline__ void gemmT(const float* sM, const float* sA, float* sT)
{
    const int t  = threadIdx.x;
    const int i0 = (t >> 4) << 2;
    const int r0 = (t & 15) << 1;
    float acc[4][2] = {};
    for (int j = 0; j < 64; j += 4){
        float4 a0 = *(const float4*)(sA + r0*68     + j);
        float4 a1 = *(const float4*)(sA + (r0+1)*68 + j);
#pragma unroll
        for (int a = 0; a < 4; ++a){
            float4 nv = *(const float4*)(sM + (i0+a)*68 + j);
            acc[a][0] += dot4(nv, a0);
            acc[a][1] += dot4(nv, a1);
        }
    }
#pragma unroll
    for (int a = 0; a < 4; ++a){
        sT[(i0+a)*36 + r0]     = acc[a][0];
        sT[(i0+a)*36 + r0 + 1] = acc[a][1];
    }
}

// S (32x32, stride 36) = A * T  (A operand as broadcast float4)
__device__ __forceinline__ void gemmS(const float* sA, const float* sT, float* sS)
{
    const int t  = threadIdx.x;
    const int r  = t >> 3;
    const int cb = (t & 7) << 2;
    float4 acc = make_float4(0.f,0.f,0.f,0.f);
#pragma unroll
    for (int i4 = 0; i4 < 16; ++i4){
        float4 av = *(const float4*)(sA + r*68 + 4*i4);
        float4 t0 = *(const float4*)(sT + (4*i4+0)*36 + cb);
        float4 t1 = *(const float4*)(sT + (4*i4+1)*36 + cb);
        float4 t2 = *(const float4*)(sT + (4*i4+2)*36 + cb);
        float4 t3 = *(const float4*)(sT + (4*i4+3)*36 + cb);
        acc.x += av.x*t0.x + av.y*t1.x + av.z*t2.x + av.w*t3.x;
        acc.y += av.x*t0.y + av.y*t1.y + av.z*t2.y + av.w*t3.y;
        acc.z += av.x*t0.z + av.y*t1.z + av.z*t2.z + av.w*t3.z;
        acc.w += av.x*t0.w + av.y*t1.w + av.z*t2.w + av.w*t3.w;
    }
    *(float4*)(sS + r*36 + cb) = acc;
}

// ======================= ANCHOR: d=68 (Schur), K=100 (pad 104) ==============
__device__ __forceinline__ float gA(int r, int c, const float* sM, const float* sT,
                                    const float* sS, const float* sW, const float* sV,
                                    const float* sXi)
{
    if (c >= 100) return 0.f;
    if (r < 64){
        if (c < 64) return sM[r*68 + c];
        if (c < 92) return sT[r*36 + (c-64)];
        if (c < 96) return sT[r*36 + 28 + (c-92)] + sW[r*4 + (c-92)];
        return -sW[r*4 + (c-96)];
    }
    if (r < 92){ int i = r-64;
        if (c < 64) return sT[c*36 + i];
        if (c < 92) return sS[i*36 + (c-64)];
        if (c < 96) return sS[i*36 + 28 + (c-92)] + sV[i*4 + (c-92)];
        return -sV[i*4 + (c-96)];
    }
    if (r < 96){ int m = r-92, i = 28+m;
        if (c < 64) return sT[c*36 + i] + sW[c*4 + m];
        if (c < 92) return sS[i*36 + (c-64)] + sV[(c-64)*4 + m];
        if (c < 96){ int j = c-92;
            return sS[i*36 + 28 + j] + sV[i*4 + j] + sV[(28+j)*4 + m] + sXi[m*4 + j]; }
        { int j = c-96; return -sV[i*4 + j] - sXi[m*4 + j]; }
    }
    { int m = r-96;
        if (c < 64) return -sW[c*4 + m];
        if (c < 92) return -sV[(c-64)*4 + m];
        if (c < 96){ int j = c-92; return -sV[(28+j)*4 + m] - sXi[m*4 + j]; }
        { int j = c-96; return sXi[m*4 + j]; }
    }
}

__global__ void __launch_bounds__(TPB, 3)
anchor_kernel(const float* __restrict__ xr, const float* __restrict__ Ain,
              const float* __restrict__ bin)
{
    extern __shared__ float sm[];
    float* sA  = sm;             // 32*68
    float* sM  = sA  + 2176;     // 64*68
    float* sT  = sM  + 4352;     // 64*36
    float* sS  = sT  + 2304;     // 32*36
    float* sY  = sS  + 1152;     // 64*4
    float* sW  = sY  + 256;      // 64*4
    float* sU  = sW  + 256;      // 32*4
    float* sV  = sU  + 128;      // 32*4
    float* sXi = sV  + 128;      // 16
    float* sv  = sXi + 16;       // 2*104
    float* su0 = sv  + 208;      // 68
    float* sdx = su0 + 68;       // 68
    float* sxr = sdx + 68;       // 64
    float* bR1 = sxr + 64;       // 128
    float* bR2 = bR1 + 128;      // 128
    float* bC1 = bR2 + 128;      // 128
    float* bC2 = bC1 + 128;      // 128

    const int p = blockIdx.x;
    const int t = threadIdx.x;
    const float* Ap = Ain + (size_t)p * 2048;
    const float* bp = bin + (size_t)p * 32;

    for (int e = t; e < 2048; e += TPB) sA[(e>>6)*68 + (e&63)] = Ap[e];
    if (t < 64) sxr[t] = xr[(size_t)p*64 + t];
    if (t >= 64 && t < 72){ int q = t-64; sv[100 + (q&3) + (q>>2)*104] = 0.f; }
    __syncthreads();

    gj64_reg2(sA, sM, 2.0f + SIGMA_, bR1, bR2, bC1, bC2);
    gemmT(sM, sA, sT);
    __syncthreads();
    gemmS(sA, sT, sS);
    __syncthreads();

    if (t == 0){
        float X[4][4];
        for (int m = 0; m < 4; ++m)
            for (int j = 0; j < 4; ++j)
                X[m][j] = ((m==j) ? (4.0f+SIGMA_) : 0.f) - sS[(28+m)*36 + 28 + j];
        for (int k = 0; k < 4; ++k){
            float pinv = 1.0f / X[k][k];
            for (int j = 0; j < 4; ++j) if (j != k) X[k][j] *= pinv;
            X[k][k] = pinv;
            for (int i = 0; i < 4; ++i) if (i != k){
                float f = X[i][k];
                for (int j = 0; j < 4; ++j) if (j != k) X[i][j] -= f * X[k][j];
                X[i][k] = -f * pinv;
            }
        }
        for (int m = 0; m < 4; ++m)
            for (int j = 0; j < 4; ++j) sXi[m*4+j] = X[m][j];
    }
    __syncthreads();
    if (t < 64){
        float y[4];
#pragma unroll
        for (int m = 0; m < 4; ++m){ y[m] = -sT[t*36 + 28 + m]; sY[t*4+m] = y[m]; }
#pragma unroll
        for (int m = 0; m < 4; ++m){
            float a = 0.f;
#pragma unroll
            for (int j = 0; j < 4; ++j) a += y[j] * sXi[j*4+m];
            sW[t*4+m] = a;
        }
    } else if (t < 96){
        int r = t - 64;
        float u[4];
#pragma unroll
        for (int m = 0; m < 4; ++m){ u[m] = -sS[r*36 + 28 + m]; sU[r*4+m] = u[m]; }
#pragma unroll
        for (int m = 0; m < 4; ++m){
            float a = 0.f;
#pragma unroll
            for (int j = 0; j < 4; ++j) a += u[j] * sXi[j*4+m];
            sV[r*4+m] = a;
        }
    }
    __syncthreads();
    for (int e = t; e < 4096; e += TPB){
        int i = e >> 6, j = e & 63; float a = 0.f;
#pragma unroll
        for (int m = 0; m < 4; ++m) a += sW[i*4+m] * sY[j*4+m];
        sM[i*68 + j] += a;
    }
    for (int e = t; e < 2048; e += TPB){
        int i = e >> 5, a0 = e & 31; float a = 0.f;
#pragma unroll
        for (int m = 0; m < 4; ++m) a += sW[i*4+m] * sU[a0*4+m];
        sT[i*36 + a0] += a;
    }
    for (int e = t; e < 1024; e += TPB){
        int r = e >> 5, c = e & 31; float a = 0.f;
#pragma unroll
        for (int m = 0; m < 4; ++m) a += sV[r*4+m] * sU[c*4+m];
        sS[r*36 + c] += a;
    }
    __syncthreads();
    if (t < 64) su0[t] = dotA(sM, t, sxr);
    else if (t < 68){
        int m = t - 64; float a = 0.f;
        for (int j = 0; j < 64; ++j) a -= sW[j*4+m] * sxr[j];
        su0[64+m] = a;
    }
    __syncthreads();

    const int row = t >> 1, h = t & 1;
    float lo = 0.f, hi = 0.f, cx0 = 0.f;
    if (t < 200){
        if (row < 64){ lo = 0.f; hi = INFINITY; cx0 = su0[row]; }
        else if (row < 92){ int i = row-64; lo = -INFINITY; hi = bp[i]; cx0 = dotA(sA, i, su0); }
        else if (row < 96){ int m = row-92; int i = 28+m;
            lo = -INFINITY; hi = bp[i]; cx0 = dotA(sA, i, su0) - su0[64+m]; }
        else { int m = row-96; lo = 0.f; hi = INFINITY; cx0 = su0[64+m]; }
    }
    unsigned long long G2[26];
    if (t < 200){
#pragma unroll
        for (int c2 = 0; c2 < 26; ++c2){
            float g0 = gA(row, h*52 + 2*c2,     sM, sT, sS, sW, sV, sXi);
            float g1 = gA(row, h*52 + 2*c2 + 1, sM, sT, sS, sW, sV, sXi);
            PACK2(G2[c2], g0, g1);
        }
    }
    __syncthreads();

    float z = fminf(fmaxf(0.f, lo), hi), y = 0.f;
    for (int it = 0; it < ITERS; ++it){
        float* vb = sv + (it & 1) * 104;
        if (t < 200 && h == 0) vb[row] = z - y;
        __syncthreads();
        const ulonglong2* v2 = (const ulonglong2*)vb + h*13;
        unsigned long long a0 = 0ull, a1 = 0ull, a2 = 0ull, a3 = 0ull;
#pragma unroll
        for (int c = 0; c < 13; ++c){
            ulonglong2 vv = v2[c];
            if (c & 1){ FMA2(a2, G2[2*c], vv.x); FMA2(a3, G2[2*c+1], vv.y); }
            else      { FMA2(a0, G2[2*c], vv.x); FMA2(a1, G2[2*c+1], vv.y); }
        }
        float x0, x1, x2, x3, x4, x5, x6, x7;
        UNPK2(x0, x1, a0); UNPK2(x2, x3, a1); UNPK2(x4, x5, a2); UNPK2(x6, x7, a3);
        float acc = ((x0+x1)+(x2+x3)) + ((x4+x5)+(x6+x7));
        acc += __shfl_xor_sync(0xFFFFFFFFu, acc, 1);
        float Cx = cx0 + acc;
        float zn = fminf(fmaxf(Cx + y, lo), hi);
        y += Cx - zn; z = zn;
    }
    __syncthreads();

    const float* vl = sv + ((ITERS-1) & 1) * 104;
    if (t < 64){
        float a = vl[t];
        for (int r = 0; r < 28; ++r) a += sA[r*68 + t] * vl[64+r];
#pragma unroll
        for (int r = 28; r < 32; ++r) a += sA[r*68 + t] * vl[92 + (r-28)];
        sdx[t] = a;
    } else if (t < 68){
        int m = t - 64; sdx[64+m] = vl[96+m] - vl[92+m];
    }
    __syncthreads();
    if (t < 64){
        float a = su0[t] + dotA(sM, t, sdx);
#pragma unroll
        for (int m = 0; m < 4; ++m) a -= sW[t*4+m] * sdx[64+m];
        g_xfeas[(size_t)p*64 + t] = a;
    }
}

// ======================= LMO: d=64, K=96 ====================================
__global__ void __launch_bounds__(TPB, 3)
lmo_kernel(const float* __restrict__ Ain, const float* __restrict__ bin,
           const float* __restrict__ W1, const float* __restrict__ w2,
           float* __restrict__ out)
{
    extern __shared__ float sm[];
    float* sA  = sm;             // 32*68 (normalized)
    float* sM  = sA  + 2176;     // 64*68
    float* sT  = sM  + 4352;     // 64*36
    float* sS  = sT  + 2304;     // 32*36
    float* sv  = sS  + 1152;     // 2*96
    float* su0 = sv  + 192;      // 64
    float* sd  = su0 + 64;       // 64
    float* sx  = sd  + 64;       // 64
    float* shb = sx  + 64;       // 256
    float* sg  = shb + 256;      // 64
    float* srv = sg  + 64;       // 32
    float* bR1 = srv + 32;       // 128
    float* bR2 = bR1 + 128;      // 128
    float* bC1 = bR2 + 128;      // 128
    float* bC2 = bC1 + 128;      // 128

    const int p = blockIdx.x;
    const int t = threadIdx.x;
    const float* Ap = Ain + (size_t)p * 2048;
    const float* bp = bin + (size_t)p * 32;

    for (int e = t; e < 2048; e += TPB) sA[(e>>6)*68 + (e&63)] = Ap[e];
    if (t < 64) sx[t] = g_xfeas[(size_t)p*64 + t];
    __syncthreads();

    if (t < 32){
        float ss = 0.f;
        const float* Ar = sA + t*68;
        for (int i = 0; i < 64; ++i) ss += Ar[i]*Ar[i];
        srv[t] = 1.0f / fmaxf(sqrtf(ss), 1e-12f);
    }
    {
        float a = 0.f;
        for (int i = 0; i < 64; ++i) a += sx[i] * W1[i*256 + t];
        float hh = tanhf(a);
        shb[t] = (1.f - hh*hh) * w2[t];
    }
    __syncthreads();
    for (int e = t; e < 2048; e += TPB){
        int r = e >> 6;
        sA[r*68 + (e&63)] *= srv[r];
    }
    {
        int wid = t >> 5, lane = t & 31;
        for (int rr = 0; rr < 8; ++rr){
            int i = wid*8 + rr;
            const float* Wr = W1 + i*256;
            float a = 0.f;
#pragma unroll
            for (int k = 0; k < 8; ++k) a += Wr[k*32 + lane] * shb[k*32 + lane];
#pragma unroll
            for (int o = 16; o; o >>= 1) a += __shfl_xor_sync(0xFFFFFFFFu, a, o);
            if (lane == 0) sg[i] = a;
        }
    }
    __syncthreads();

    gj64_reg2(sA, sM, 1.0f + EPSLMO_ + SIGMA_, bR1, bR2, bC1, bC2);
    gemmT(sM, sA, sT);
    __syncthreads();
    gemmS(sA, sT, sS);
    if (t < 64) su0[t] = dotA(sM, t, sg);
    __syncthreads();

    const int row = t >> 1, h = t & 1;
    float lo = 0.f, hi = 0.f, cx0 = 0.f;
    if (t < 192){
        if (row < 64){ lo = 0.f; hi = INFINITY; cx0 = su0[row]; }
        else { int a = row - 64; lo = -INFINITY; hi = bp[a] * srv[a]; cx0 = dotA(sA, a, su0); }
    }
    unsigned long long G2[24];
    if (t < 192){
#pragma unroll
        for (int c2 = 0; c2 < 24; ++c2){
            int c0 = h*48 + 2*c2, c1 = c0 + 1;
            float g0, g1;
            if (row < 64){
                g0 = (c0 < 64) ? sM[row*68 + c0] : sT[row*36 + (c0-64)];
                g1 = (c1 < 64) ? sM[row*68 + c1] : sT[row*36 + (c1-64)];
            } else {
                int a = row - 64;
                g0 = (c0 < 64) ? sT[c0*36 + a] : sS[a*36 + (c0-64)];
                g1 = (c1 < 64) ? sT[c1*36 + a] : sS[a*36 + (c1-64)];
            }
            PACK2(G2[c2], g0, g1);
        }
    }
    __syncthreads();

    float z = fminf(fmaxf(0.f, lo), hi), y = 0.f;
    for (int it = 0; it < ITERS; ++it){
        float* vb = sv + (it & 1) * 96;
        if (t < 192 && h == 0) vb[row] = z - y;
        __syncthreads();
        const ulonglong2* v2 = (const ulonglong2*)vb + h*12;
        unsigned long long a0 = 0ull, a1 = 0ull, a2 = 0ull, a3 = 0ull;
#pragma unroll
        for (int c = 0; c < 12; ++c){
            ulonglong2 vv = v2[c];
            if (c & 1){ FMA2(a2, G2[2*c], vv.x); FMA2(a3, G2[2*c+1], vv.y); }
            else      { FMA2(a0, G2[2*c], vv.x); FMA2(a1, G2[2*c+1], vv.y); }
        }
        float x0, x1, x2, x3, x4, x5, x6, x7;
        UNPK2(x0, x1, a0); UNPK2(x2, x3, a1); UNPK2(x4, x5, a2); UNPK2(x6, x7, a3);
        float acc = ((x0+x1)+(x2+x3)) + ((x4+x5)+(x6+x7));
        acc += __shfl_xor_sync(0xFFFFFFFFu, acc, 1);
        float Cx = cx0 + acc;
        float zn = fminf(fmaxf(Cx + y, lo), hi);
        y += Cx - zn; z = zn;
    }
    __syncthreads();

    const float* vl = sv + ((ITERS-1) & 1) * 96;
    if (t < 64){
        float a = vl[t];
        for (int r = 0; r < 32; ++r) a += sA[r*68 + t] * vl[64+r];
        sd[t] = a;
    }
    __syncthreads();
    if (t < 64){
        float c_sol = su0[t] + dotA(sM, t, sd);
        out[(size_t)p*64 + t] = 0.9f * sx[t] + 0.1f * c_sol;
    }
}

// ---------------------------------------------------------------------------
extern "C" void kernel_launch(void* const* d_in, const int* in_sizes, int n_in,
                              void* d_out, int out_size)
{
    const float* xr = (const float*)d_in[0];
    const float* A  = (const float*)d_in[1];
    const float* b  = (const float*)d_in[2];
    const float* W1 = (const float*)d_in[3];
    const float* w2 = (const float*)d_in[4];
    float* out = (float*)d_out;

    const int a_smem = (2176 + 4352 + 2304 + 1152 + 256 + 256 + 128 + 128 + 16
                        + 208 + 68 + 68 + 64 + 512) * (int)sizeof(float);
    const int l_smem = (2176 + 4352 + 2304 + 1152 + 192 + 64 + 64 + 64 + 256
                        + 64 + 32 + 512) * (int)sizeof(float);

    cudaFuncSetAttribute(anchor_kernel, cudaFuncAttributeMaxDynamicSharedMemorySize, a_smem);
    cudaFuncSetAttribute(lmo_kernel,    cudaFuncAttributeMaxDynamicSharedMemorySize, l_smem);

    anchor_kernel<<<NPROB, TPB, a_smem>>>(xr, A, b);
    lmo_kernel<<<NPROB, TPB, l_smem>>>(A, b, W1, w2, out);
}

// round 12
// speedup vs baseline: 1.0753x; 1.0446x over previous
#include <cuda_runtime.h>
#include <math.h>

#define NPROB 4096
#define TPB   256
#define ITERS 80
static constexpr float SIGMA_  = 1e-6f;
static constexpr float EPSLMO_ = 1e-4f;

__device__ float g_xfeas[NPROB * 64];

#define FMA2(d,a,b)  asm("fma.rn.f32x2 %0, %1, %2, %0;" : "+l"(d) : "l"(a), "l"(b))
#define PACK2(d,x,y) asm("mov.b64 %0, {%1, %2};" : "=l"(d) : "f"(x), "f"(y))
#define UNPK2(x,y,v) asm("mov.b64 {%0, %1}, %2;" : "=f"(x), "=f"(y) : "l"(v))
#define BARX(id,n)   asm volatile("bar.sync %0, %1;" :: "r"(id), "r"(n) : "memory")

__device__ __forceinline__ float dot4(float4 a, float4 b){
    return a.x*b.x + a.y*b.y + a.z*b.z + a.w*b.w;
}
__device__ __forceinline__ float dotA(const float* sA, int i, const float* v){
    const float4* a4 = (const float4*)(sA + i*68);
    const float4* v4 = (const float4*)v;
    float s = 0.f;
#pragma unroll
    for (int q = 0; q < 16; ++q) s += dot4(a4[q], v4[q]);
    return s;
}

// ---------------------------------------------------------------------------
// Register-resident GJ inverse of M = diag*I + A^T A (64x64), result -> sM.
// Thread t: row gi = t&63, cols [j0, j0+16), j0 = (t>>6)*16, in R[16].
// (R9-proven single-pivot version.)
// ---------------------------------------------------------------------------
__device__ __forceinline__ void gj64_reg(const float* sA, float* sM, float diag,
                                         float* bufRow, float* bufCol, float* bufPinv)
{
    const int t  = threadIdx.x;
    const int gi = t & 63;
    const int cb = t >> 6;
    const int j0 = cb << 4;

    float R[16];
#pragma unroll
    for (int l = 0; l < 16; ++l) R[l] = 0.f;
    for (int r = 0; r < 32; ++r){
        float  ag = sA[r*68 + gi];
        float4 a0 = *(const float4*)(sA + r*68 + j0);
        float4 a1 = *(const float4*)(sA + r*68 + j0 + 4);
        float4 a2 = *(const float4*)(sA + r*68 + j0 + 8);
        float4 a3 = *(const float4*)(sA + r*68 + j0 + 12);
        R[0]+=ag*a0.x; R[1]+=ag*a0.y; R[2]+=ag*a0.z; R[3]+=ag*a0.w;
        R[4]+=ag*a1.x; R[5]+=ag*a1.y; R[6]+=ag*a1.z; R[7]+=ag*a1.w;
        R[8]+=ag*a2.x; R[9]+=ag*a2.y; R[10]+=ag*a2.z; R[11]+=ag*a2.w;
        R[12]+=ag*a3.x; R[13]+=ag*a3.y; R[14]+=ag*a3.z; R[15]+=ag*a3.w;
    }
    if ((gi >> 4) == cb){
#pragma unroll
        for (int l = 0; l < 16; ++l) if ((gi & 15) == l) R[l] += diag;
    }
    if (gi == 0){
        *(float4*)(bufRow + j0)      = make_float4(R[0],R[1],R[2],R[3]);
        *(float4*)(bufRow + j0 + 4)  = make_float4(R[4],R[5],R[6],R[7]);
        *(float4*)(bufRow + j0 + 8)  = make_float4(R[8],R[9],R[10],R[11]);
        *(float4*)(bufRow + j0 + 12) = make_float4(R[12],R[13],R[14],R[15]);
        if (cb == 0) bufPinv[0] = __frcp_rn(R[0]);
    }
    if (cb == 0) bufCol[gi] = R[0];
    __syncthreads();

    for (int ko = 0; ko < 4; ++ko){
#pragma unroll
        for (int ki = 0; ki < 16; ++ki){
            const int k = ko*16 + ki;
            const int b = ki & 1;
            float pinv = bufPinv[b];
            float pc   = bufCol[b*64 + gi];
            const bool isk = (gi == k);
            float fac = isk ? pinv : (-pc * pinv);
#pragma unroll
            for (int q = 0; q < 4; ++q){
                float4 p = *(const float4*)(bufRow + b*64 + j0 + 4*q);
                if (isk){
                    R[4*q+0] = p.x*fac; R[4*q+1] = p.y*fac;
                    R[4*q+2] = p.z*fac; R[4*q+3] = p.w*fac;
                } else {
                    R[4*q+0] += p.x*fac; R[4*q+1] += p.y*fac;
                    R[4*q+2] += p.z*fac; R[4*q+3] += p.w*fac;
                }
            }
            if (ko == cb) R[ki] = isk ? pinv : fac;
            if (k < 63){
                const int kn  = k + 1;
                const int bn  = kn & 1;
                const int kol = (ki == 15) ? (ko + 1) : ko;
                const int lnl = (ki + 1) & 15;
                if (gi == kn){
                    *(float4*)(bufRow + bn*64 + j0)      = make_float4(R[0],R[1],R[2],R[3]);
                    *(float4*)(bufRow + bn*64 + j0 + 4)  = make_float4(R[4],R[5],R[6],R[7]);
                    *(float4*)(bufRow + bn*64 + j0 + 8)  = make_float4(R[8],R[9],R[10],R[11]);
                    *(float4*)(bufRow + bn*64 + j0 + 12) = make_float4(R[12],R[13],R[14],R[15]);
                    if (kol == cb) bufPinv[bn] = __frcp_rn(R[lnl]);
                }
                if (kol == cb) bufCol[bn*64 + gi] = R[lnl];
            }
            __syncthreads();
        }
    }
    *(float4*)(sM + gi*68 + j0)      = make_float4(R[0],R[1],R[2],R[3]);
    *(float4*)(sM + gi*68 + j0 + 4)  = make_float4(R[4],R[5],R[6],R[7]);
    *(float4*)(sM + gi*68 + j0 + 8)  = make_float4(R[8],R[9],R[10],R[11]);
    *(float4*)(sM + gi*68 + j0 + 12) = make_float4(R[12],R[13],R[14],R[15]);
    __syncthreads();
}

// T (64x32, stride 36) = N * A^T
__device__ __forceinline__ void gemmT(const float* sM, const float* sA, float* sT)
{
    const int t  = threadIdx.x;
    const int i0 = (t >> 4) << 2;
    const int r0 = (t & 15) << 1;
    float acc[4][2] = {};
    for (int j = 0; j < 64; j += 4){
        float4 a0 = *(const float4*)(sA + r0*68     + j);
        float4 a1 = *(const float4*)(sA + (r0+1)*68 + j);
#pragma unroll
        for (int a = 0; a < 4; ++a){
            float4 nv = *(const float4*)(sM + (i0+a)*68 + j);
            acc[a][0] += dot4(nv, a0);
            acc[a][1] += dot4(nv, a1);
        }
    }
#pragma unroll
    for (int a = 0; a < 4; ++a){
        sT[(i0+a)*36 + r0]     = acc[a][0];
        sT[(i0+a)*36 + r0 + 1] = acc[a][1];
    }
}

// S (32x32, stride 36) = A * T  (A operand as broadcast float4)
__device__ __forceinline__ void gemmS(const float* sA, const float* sT, float* sS)
{
    const int t  = threadIdx.x;
    const int r  = t >> 3;
    const int cb = (t & 7) << 2;
    float4 acc = make_float4(0.f,0.f,0.f,0.f);
#pragma unroll
    for (int i4 = 0; i4 < 16; ++i4){
        float4 av = *(const float4*)(sA + r*68 + 4*i4);
        float4 t0 = *(const float4*)(sT + (4*i4+0)*36 + cb);
        float4 t1 = *(const float4*)(sT + (4*i4+1)*36 + cb);
        float4 t2 = *(const float4*)(sT + (4*i4+2)*36 + cb);
        float4 t3 = *(const float4*)(sT + (4*i4+3)*36 + cb);
        acc.x += av.x*t0.x + av.y*t1.x + av.z*t2.x + av.w*t3.x;
        acc.y += av.x*t0.y + av.y*t1.y + av.z*t2.y + av.w*t3.y;
        acc.z += av.x*t0.z + av.y*t1.z + av.z*t2.z + av.w*t3.z;
        acc.w += av.x*t0.w + av.y*t1.w + av.z*t2.w + av.w*t3.w;
    }
    *(float4*)(sS + r*36 + cb) = acc;
}

// ======================= ANCHOR: d=68 (Schur), K=100 (pad 104) ==============
__device__ __forceinline__ float gA(int r, int c, const float* sM, const float* sT,
                                    const float* sS, const float* sW, const float* sV,
                                    const float* sXi)
{
    if (c >= 100) return 0.f;
    if (r < 64){
        if (c < 64) return sM[r*68 + c];
        if (c < 92) return sT[r*36 + (c-64)];
        if (c < 96) return sT[r*36 + 28 + (c-92)] + sW[r*4 + (c-92)];
        return -sW[r*4 + (c-96)];
    }
    if (r < 92){ int i = r-64;
        if (c < 64) return sT[c*36 + i];
        if (c < 92) return sS[i*36 + (c-64)];
        if (c < 96) return sS[i*36 + 28 + (c-92)] + sV[i*4 + (c-92)];
        return -sV[i*4 + (c-96)];
    }
    if (r < 96){ int m = r-92, i = 28+m;
        if (c < 64) return sT[c*36 + i] + sW[c*4 + m];
        if (c < 92) return sS[i*36 + (c-64)] + sV[(c-64)*4 + m];
        if (c < 96){ int j = c-92;
            return sS[i*36 + 28 + j] + sV[i*4 + j] + sV[(28+j)*4 + m] + sXi[m*4 + j]; }
        { int j = c-96; return -sV[i*4 + j] - sXi[m*4 + j]; }
    }
    { int m = r-96;
        if (c < 64) return -sW[c*4 + m];
        if (c < 92) return -sV[(c-64)*4 + m];
        if (c < 96){ int j = c-92; return -sV[(28+j)*4 + m] - sXi[m*4 + j]; }
        { int j = c-96; return sXi[m*4 + j]; }
    }
}

__global__ void __launch_bounds__(TPB, 3)
anchor_kernel(const float* __restrict__ xr, const float* __restrict__ Ain,
              const float* __restrict__ bin)
{
    extern __shared__ float sm[];
    float* sA  = sm;             // 32*68
    float* sM  = sA  + 2176;     // 64*68
    float* sT  = sM  + 4352;     // 64*36
    float* sS  = sT  + 2304;     // 32*36
    float* sY  = sS  + 1152;     // 64*4
    float* sW  = sY  + 256;      // 64*4
    float* sU  = sW  + 256;      // 32*4
    float* sV  = sU  + 128;      // 32*4
    float* sXi = sV  + 128;      // 16
    float* sv  = sXi + 16;       // 2*104
    float* su0 = sv  + 208;      // 68
    float* sdx = su0 + 68;       // 68
    float* sxr = sdx + 68;       // 64
    float* bR  = sxr + 64;       // 128
    float* bC  = bR  + 128;      // 128
    float* bP  = bC  + 128;      // 2 + pad

    const int p = blockIdx.x;
    const int t = threadIdx.x;
    const float* Ap = Ain + (size_t)p * 2048;
    const float* bp = bin + (size_t)p * 32;

    for (int e = t; e < 2048; e += TPB) sA[(e>>6)*68 + (e&63)] = Ap[e];
    if (t < 64) sxr[t] = xr[(size_t)p*64 + t];
    if (t >= 64 && t < 72){ int q = t-64; sv[100 + (q&3) + (q>>2)*104] = 0.f; }
    __syncthreads();

    gj64_reg(sA, sM, 2.0f + SIGMA_, bR, bC, bP);
    gemmT(sM, sA, sT);
    __syncthreads();
    gemmS(sA, sT, sS);
    __syncthreads();

    if (t == 0){
        float X[4][4];
        for (int m = 0; m < 4; ++m)
            for (int j = 0; j < 4; ++j)
                X[m][j] = ((m==j) ? (4.0f+SIGMA_) : 0.f) - sS[(28+m)*36 + 28 + j];
        for (int k = 0; k < 4; ++k){
            float pinv = 1.0f / X[k][k];
            for (int j = 0; j < 4; ++j) if (j != k) X[k][j] *= pinv;
            X[k][k] = pinv;
            for (int i = 0; i < 4; ++i) if (i != k){
                float f = X[i][k];
                for (int j = 0; j < 4; ++j) if (j != k) X[i][j] -= f * X[k][j];
                X[i][k] = -f * pinv;
            }
        }
        for (int m = 0; m < 4; ++m)
            for (int j = 0; j < 4; ++j) sXi[m*4+j] = X[m][j];
    }
    __syncthreads();
    if (t < 64){
        float y[4];
#pragma unroll
        for (int m = 0; m < 4; ++m){ y[m] = -sT[t*36 + 28 + m]; sY[t*4+m] = y[m]; }
#pragma unroll
        for (int m = 0; m < 4; ++m){
            float a = 0.f;
#pragma unroll
            for (int j = 0; j < 4; ++j) a += y[j] * sXi[j*4+m];
            sW[t*4+m] = a;
        }
    } else if (t < 96){
        int r = t - 64;
        float u[4];
#pragma unroll
        for (int m = 0; m < 4; ++m){ u[m] = -sS[r*36 + 28 + m]; sU[r*4+m] = u[m]; }
#pragma unroll
        for (int m = 0; m < 4; ++m){
            float a = 0.f;
#pragma unroll
            for (int j = 0; j < 4; ++j) a += u[j] * sXi[j*4+m];
            sV[r*4+m] = a;
        }
    }
    __syncthreads();
    for (int e = t; e < 4096; e += TPB){
        int i = e >> 6, j = e & 63; float a = 0.f;
#pragma unroll
        for (int m = 0; m < 4; ++m) a += sW[i*4+m] * sY[j*4+m];
        sM[i*68 + j] += a;
    }
    for (int e = t; e < 2048; e += TPB){
        int i = e >> 5, a0 = e & 31; float a = 0.f;
#pragma unroll
        for (int m = 0; m < 4; ++m) a += sW[i*4+m] * sU[a0*4+m];
        sT[i*36 + a0] += a;
    }
    for (int e = t; e < 1024; e += TPB){
        int r = e >> 5, c = e & 31; float a = 0.f;
#pragma unroll
        for (int m = 0; m < 4; ++m) a += sV[r*4+m] * sU[c*4+m];
        sS[r*36 + c] += a;
    }
    __syncthreads();
    if (t < 64) su0[t] = dotA(sM, t, sxr);
    else if (t < 68){
        int m = t - 64; float a = 0.f;
        for (int j = 0; j < 64; ++j) a -= sW[j*4+m] * sxr[j];
        su0[64+m] = a;
    }
    __syncthreads();

    const int row = t >> 1, h = t & 1;
    const int wid = t >> 5;
    float lo = 0.f, hi = 0.f, cx0 = 0.f;
    if (t < 200){
        if (row < 64){ lo = 0.f; hi = INFINITY; cx0 = su0[row]; }
        else if (row < 92){ int i = row-64; lo = -INFINITY; hi = bp[i]; cx0 = dotA(sA, i, su0); }
        else if (row < 96){ int m = row-92; int i = 28+m;
            lo = -INFINITY; hi = bp[i]; cx0 = dotA(sA, i, su0) - su0[64+m]; }
        else { int m = row-96; lo = 0.f; hi = INFINITY; cx0 = su0[64+m]; }
    }
    unsigned long long G2[26];
    if (t < 200){
#pragma unroll
        for (int c2 = 0; c2 < 26; ++c2){
            float g0 = gA(row, h*52 + 2*c2,     sM, sT, sS, sW, sV, sXi);
            float g1 = gA(row, h*52 + 2*c2 + 1, sM, sT, sS, sW, sV, sXi);
            PACK2(G2[c2], g0, g1);
        }
    }
    __syncthreads();

    // ADMM loop: warps 0..6 only (224 threads, named barrier 1); warp 7 waits.
    if (wid < 7){
        const unsigned smask = (wid == 6) ? 0xFFu : 0xFFFFFFFFu;
        float z = fminf(fmaxf(0.f, lo), hi), y = 0.f;
        for (int it = 0; it < ITERS; ++it){
            float* vb = sv + (it & 1) * 104;
            if (t < 200 && h == 0) vb[row] = z - y;
            BARX(1, 224);
            if (t < 200){
                const ulonglong2* v2 = (const ulonglong2*)vb + h*13;
                unsigned long long a0 = 0ull, a1 = 0ull, a2 = 0ull, a3 = 0ull;
#pragma unroll
                for (int c = 0; c < 13; ++c){
                    ulonglong2 vv = v2[c];
                    if (c & 1){ FMA2(a2, G2[2*c], vv.x); FMA2(a3, G2[2*c+1], vv.y); }
                    else      { FMA2(a0, G2[2*c], vv.x); FMA2(a1, G2[2*c+1], vv.y); }
                }
                float x0, x1, x2, x3, x4, x5, x6, x7;
                UNPK2(x0, x1, a0); UNPK2(x2, x3, a1); UNPK2(x4, x5, a2); UNPK2(x6, x7, a3);
                float acc = ((x0+x1)+(x2+x3)) + ((x4+x5)+(x6+x7));
                acc += __shfl_xor_sync(smask, acc, 1);
                float Cx = cx0 + acc;
                float zn = fminf(fmaxf(Cx + y, lo), hi);
                y += Cx - zn; z = zn;
            }
        }
    }
    __syncthreads();

    const float* vl = sv + ((ITERS-1) & 1) * 104;
    if (t < 64){
        float a = vl[t];
        for (int r = 0; r < 28; ++r) a += sA[r*68 + t] * vl[64+r];
#pragma unroll
        for (int r = 28; r < 32; ++r) a += sA[r*68 + t] * vl[92 + (r-28)];
        sdx[t] = a;
    } else if (t < 68){
        int m = t - 64; sdx[64+m] = vl[96+m] - vl[92+m];
    }
    __syncthreads();
    if (t < 64){
        float a = su0[t] + dotA(sM, t, sdx);
#pragma unroll
        for (int m = 0; m < 4; ++m) a -= sW[t*4+m] * sdx[64+m];
        g_xfeas[(size_t)p*64 + t] = a;
    }
}

// ======================= LMO: d=64, K=96 ====================================
__global__ void __launch_bounds__(TPB, 3)
lmo_kernel(const float* __restrict__ Ain, const float* __restrict__ bin,
           const float* __restrict__ W1, const float* __restrict__ w2,
           float* __restrict__ out)
{
    extern __shared__ float sm[];
    float* sA  = sm;             // 32*68 (normalized)
    float* sM  = sA  + 2176;     // 64*68
    float* sT  = sM  + 4352;     // 64*36
    float* sS  = sT  + 2304;     // 32*36
    float* sv  = sS  + 1152;     // 2*96
    float* su0 = sv  + 192;      // 64
    float* sd  = su0 + 64;       // 64
    float* sx  = sd  + 64;       // 64
    float* shb = sx  + 64;       // 256
    float* sg  = shb + 256;      // 64
    float* srv = sg  + 64;       // 32
    float* bR  = srv + 32;       // 128
    float* bC  = bR  + 128;      // 128
    float* bP  = bC  + 128;      // 2 + pad

    const int p = blockIdx.x;
    const int t = threadIdx.x;
    const float* Ap = Ain + (size_t)p * 2048;
    const float* bp = bin + (size_t)p * 32;

    for (int e = t; e < 2048; e += TPB) sA[(e>>6)*68 + (e&63)] = Ap[e];
    if (t < 64) sx[t] = g_xfeas[(size_t)p*64 + t];
    __syncthreads();

    if (t < 32){
        float ss = 0.f;
        const float* Ar = sA + t*68;
        for (int i = 0; i < 64; ++i) ss += Ar[i]*Ar[i];
        srv[t] = 1.0f / fmaxf(sqrtf(ss), 1e-12f);
    }
    {
        float a = 0.f;
        for (int i = 0; i < 64; ++i) a += sx[i] * W1[i*256 + t];
        float hh = tanhf(a);
        shb[t] = (1.f - hh*hh) * w2[t];
    }
    __syncthreads();
    for (int e = t; e < 2048; e += TPB){
        int r = e >> 6;
        sA[r*68 + (e&63)] *= srv[r];
    }
    {
        int wd = t >> 5, lane = t & 31;
        for (int rr = 0; rr < 8; ++rr){
            int i = wd*8 + rr;
            const float* Wr = W1 + i*256;
            float a = 0.f;
#pragma unroll
            for (int k = 0; k < 8; ++k) a += Wr[k*32 + lane] * shb[k*32 + lane];
#pragma unroll
            for (int o = 16; o; o >>= 1) a += __shfl_xor_sync(0xFFFFFFFFu, a, o);
            if (lane == 0) sg[i] = a;
        }
    }
    __syncthreads();

    gj64_reg(sA, sM, 1.0f + EPSLMO_ + SIGMA_, bR, bC, bP);
    gemmT(sM, sA, sT);
    __syncthreads();
    gemmS(sA, sT, sS);
    if (t < 64) su0[t] = dotA(sM, t, sg);
    __syncthreads();

    const int row = t >> 1, h = t & 1;
    const int wid = t >> 5;
    float lo = 0.f, hi = 0.f, cx0 = 0.f;
    if (t < 192){
        if (row < 64){ lo = 0.f; hi = INFINITY; cx0 = su0[row]; }
        else { int a = row - 64; lo = -INFINITY; hi = bp[a] * srv[a]; cx0 = dotA(sA, a, su0); }
    }
    unsigned long long G2[24];
    if (t < 192){
#pragma unroll
        for (int c2 = 0; c2 < 24; ++c2){
            int c0 = h*48 + 2*c2, c1 = c0 + 1;
            float g0, g1;
            if (row < 64){
                g0 = (c0 < 64) ? sM[row*68 + c0] : sT[row*36 + (c0-64)];
                g1 = (c1 < 64) ? sM[row*68 + c1] : sT[row*36 + (c1-64)];
            } else {
                int a = row - 64;
                g0 = (c0 < 64) ? sT[c0*36 + a] : sS[a*36 + (c0-64)];
                g1 = (c1 < 64) ? sT[c1*36 + a] : sS[a*36 + (c1-64)];
            }
            PACK2(G2[c2], g0, g1);
        }
    }
    __syncthreads();

    // ADMM loop: warps 0..5 only (192 threads, named barrier 1); warps 6,7 wait.
    if (wid < 6){
        float z = fminf(fmaxf(0.f, lo), hi), y = 0.f;
        for (int it = 0; it < ITERS; ++it){
            float* vb = sv + (it & 1) * 96;
            if (h == 0) vb[row] = z - y;
            BARX(1, 192);
            const ulonglong2* v2 = (const ulonglong2*)vb + h*12;
            unsigned long long a0 = 0ull, a1 = 0ull, a2 = 0ull, a3 = 0ull;
#pragma unroll
            for (int c = 0; c < 12; ++c){
                ulonglong2 vv = v2[c];
                if (c & 1){ FMA2(a2, G2[2*c], vv.x); FMA2(a3, G2[2*c+1], vv.y); }
                else      { FMA2(a0, G2[2*c], vv.x); FMA2(a1, G2[2*c+1], vv.y); }
            }
            float x0, x1, x2, x3, x4, x5, x6, x7;
            UNPK2(x0, x1, a0); UNPK2(x2, x3, a1); UNPK2(x4, x5, a2); UNPK2(x6, x7, a3);
            float acc = ((x0+x1)+(x2+x3)) + ((x4+x5)+(x6+x7));
            acc += __shfl_xor_sync(0xFFFFFFFFu, acc, 1);
            float Cx = cx0 + acc;
            float zn = fminf(fmaxf(Cx + y, lo), hi);
            y += Cx - zn; z = zn;
        }
    }
    __syncthreads();

    const float* vl = sv + ((ITERS-1) & 1) * 96;
    if (t < 64){
        float a = vl[t];
        for (int r = 0; r < 32; ++r) a += sA[r*68 + t] * vl[64+r];
        sd[t] = a;
    }
    __syncthreads();
    if (t < 64){
        float c_sol = su0[t] + dotA(sM, t, sd);
        out[(size_t)p*64 + t] = 0.9f * sx[t] + 0.1f * c_sol;
    }
}

// ---------------------------------------------------------------------------
extern "C" void kernel_launch(void* const* d_in, const int* in_sizes, int n_in,
                              void* d_out, int out_size)
{
    const float* xr = (const float*)d_in[0];
    const float* A  = (const float*)d_in[1];
    const float* b  = (const float*)d_in[2];
    const float* W1 = (const float*)d_in[3];
    const float* w2 = (const float*)d_in[4];
    float* out = (float*)d_out;

    const int a_smem = (2176 + 4352 + 2304 + 1152 + 256 + 256 + 128 + 128 + 16
                        + 208 + 68 + 68 + 64 + 128 + 128 + 8) * (int)sizeof(float);
    const int l_smem = (2176 + 4352 + 2304 + 1152 + 192 + 64 + 64 + 64 + 256
                        + 64 + 32 + 128 + 128 + 8) * (int)sizeof(float);

    cudaFuncSetAttribute(anchor_kernel, cudaFuncAttributeMaxDynamicSharedMemorySize, a_smem);
    cudaFuncSetAttribute(lmo_kernel,    cudaFuncAttributeMaxDynamicSharedMemorySize, l_smem);

    anchor_kernel<<<NPROB, TPB, a_smem>>>(xr, A, b);
    lmo_kernel<<<NPROB, TPB, l_smem>>>(A, b, W1, w2, out);
}

// round 13
// speedup vs baseline: 1.0845x; 1.0086x over previous
#include <cuda_runtime.h>
#include <math.h>

#define NPROB 4096
#define TPB   256
#define ITERS 80
static constexpr float SIGMA_  = 1e-6f;
static constexpr float EPSLMO_ = 1e-4f;

__device__ float g_xfeas[NPROB * 64];

#define FMA2(d,a,b)  asm("fma.rn.f32x2 %0, %1, %2, %0;" : "+l"(d) : "l"(a), "l"(b))
#define PACK2(d,x,y) asm("mov.b64 %0, {%1, %2};" : "=l"(d) : "f"(x), "f"(y))
#define UNPK2(x,y,v) asm("mov.b64 {%0, %1}, %2;" : "=f"(x), "=f"(y) : "l"(v))
#define BARX(id,n)   asm volatile("bar.sync %0, %1;" :: "r"(id), "r"(n) : "memory")

__device__ __forceinline__ float dot4(float4 a, float4 b){
    return a.x*b.x + a.y*b.y + a.z*b.z + a.w*b.w;
}
__device__ __forceinline__ float dotA(const float* sA, int i, const float* v){
    const float4* a4 = (const float4*)(sA + i*68);
    const float4* v4 = (const float4*)v;
    float s = 0.f;
#pragma unroll
    for (int q = 0; q < 16; ++q) s += dot4(a4[q], v4[q]);
    return s;
}

// ---------------------------------------------------------------------------
// Register-resident GJ inverse of M = diag*I + A^T A (64x64), result -> sM.
// Thread t: row gi = t&63, cols [j0, j0+16), j0 = (t>>6)*16, in R[16].
// ---------------------------------------------------------------------------
__device__ __forceinline__ void gj64_reg(const float* sA, float* sM, float diag,
                                         float* bufRow, float* bufCol, float* bufPinv)
{
    const int t  = threadIdx.x;
    const int gi = t & 63;
    const int cb = t >> 6;
    const int j0 = cb << 4;

    float R[16];
#pragma unroll
    for (int l = 0; l < 16; ++l) R[l] = 0.f;
    for (int r = 0; r < 32; ++r){
        float  ag = sA[r*68 + gi];
        float4 a0 = *(const float4*)(sA + r*68 + j0);
        float4 a1 = *(const float4*)(sA + r*68 + j0 + 4);
        float4 a2 = *(const float4*)(sA + r*68 + j0 + 8);
        float4 a3 = *(const float4*)(sA + r*68 + j0 + 12);
        R[0]+=ag*a0.x; R[1]+=ag*a0.y; R[2]+=ag*a0.z; R[3]+=ag*a0.w;
        R[4]+=ag*a1.x; R[5]+=ag*a1.y; R[6]+=ag*a1.z; R[7]+=ag*a1.w;
        R[8]+=ag*a2.x; R[9]+=ag*a2.y; R[10]+=ag*a2.z; R[11]+=ag*a2.w;
        R[12]+=ag*a3.x; R[13]+=ag*a3.y; R[14]+=ag*a3.z; R[15]+=ag*a3.w;
    }
    if ((gi >> 4) == cb){
#pragma unroll
        for (int l = 0; l < 16; ++l) if ((gi & 15) == l) R[l] += diag;
    }
    if (gi == 0){
        *(float4*)(bufRow + j0)      = make_float4(R[0],R[1],R[2],R[3]);
        *(float4*)(bufRow + j0 + 4)  = make_float4(R[4],R[5],R[6],R[7]);
        *(float4*)(bufRow + j0 + 8)  = make_float4(R[8],R[9],R[10],R[11]);
        *(float4*)(bufRow + j0 + 12) = make_float4(R[12],R[13],R[14],R[15]);
        if (cb == 0) bufPinv[0] = __frcp_rn(R[0]);
    }
    if (cb == 0) bufCol[gi] = R[0];
    __syncthreads();

    for (int ko = 0; ko < 4; ++ko){
#pragma unroll
        for (int ki = 0; ki < 16; ++ki){
            const int k = ko*16 + ki;
            const int b = ki & 1;
            float pinv = bufPinv[b];
            float pc   = bufCol[b*64 + gi];
            const bool isk = (gi == k);
            float fac = isk ? pinv : (-pc * pinv);
#pragma unroll
            for (int q = 0; q < 4; ++q){
                float4 p = *(const float4*)(bufRow + b*64 + j0 + 4*q);
                if (isk){
                    R[4*q+0] = p.x*fac; R[4*q+1] = p.y*fac;
                    R[4*q+2] = p.z*fac; R[4*q+3] = p.w*fac;
                } else {
                    R[4*q+0] += p.x*fac; R[4*q+1] += p.y*fac;
                    R[4*q+2] += p.z*fac; R[4*q+3] += p.w*fac;
                }
            }
            if (ko == cb) R[ki] = isk ? pinv : fac;
            if (k < 63){
                const int kn  = k + 1;
                const int bn  = kn & 1;
                const int kol = (ki == 15) ? (ko + 1) : ko;
                const int lnl = (ki + 1) & 15;
                if (gi == kn){
                    *(float4*)(bufRow + bn*64 + j0)      = make_float4(R[0],R[1],R[2],R[3]);
                    *(float4*)(bufRow + bn*64 + j0 + 4)  = make_float4(R[4],R[5],R[6],R[7]);
                    *(float4*)(bufRow + bn*64 + j0 + 8)  = make_float4(R[8],R[9],R[10],R[11]);
                    *(float4*)(bufRow + bn*64 + j0 + 12) = make_float4(R[12],R[13],R[14],R[15]);
                    if (kol == cb) bufPinv[bn] = __frcp_rn(R[lnl]);
                }
                if (kol == cb) bufCol[bn*64 + gi] = R[lnl];
            }
            __syncthreads();
        }
    }
    *(float4*)(sM + gi*68 + j0)      = make_float4(R[0],R[1],R[2],R[3]);
    *(float4*)(sM + gi*68 + j0 + 4)  = make_float4(R[4],R[5],R[6],R[7]);
    *(float4*)(sM + gi*68 + j0 + 8)  = make_float4(R[8],R[9],R[10],R[11]);
    *(float4*)(sM + gi*68 + j0 + 12) = make_float4(R[12],R[13],R[14],R[15]);
    __syncthreads();
}

// T (64x32, stride 36) = N * A^T
__device__ __forceinline__ void gemmT(const float* sM, const float* sA, float* sT)
{
    const int t  = threadIdx.x;
    const int i0 = (t >> 4) << 2;
    const int r0 = (t & 15) << 1;
    float acc[4][2] = {};
    for (int j = 0; j < 64; j += 4){
        float4 a0 = *(const float4*)(sA + r0*68     + j);
        float4 a1 = *(const float4*)(sA + (r0+1)*68 + j);
#pragma unroll
        for (int a = 0; a < 4; ++a){
            float4 nv = *(const float4*)(sM + (i0+a)*68 + j);
            acc[a][0] += dot4(nv, a0);
            acc[a][1] += dot4(nv, a1);
        }
    }
#pragma unroll
    for (int a = 0; a < 4; ++a){
        sT[(i0+a)*36 + r0]     = acc[a][0];
        sT[(i0+a)*36 + r0 + 1] = acc[a][1];
    }
}

// S (32x32, stride 36) = A * T  (A operand as broadcast float4)
__device__ __forceinline__ void gemmS(const float* sA, const float* sT, float* sS)
{
    const int t  = threadIdx.x;
    const int r  = t >> 3;
    const int cb = (t & 7) << 2;
    float4 acc = make_float4(0.f,0.f,0.f,0.f);
#pragma unroll
    for (int i4 = 0; i4 < 16; ++i4){
        float4 av = *(const float4*)(sA + r*68 + 4*i4);
        float4 t0 = *(const float4*)(sT + (4*i4+0)*36 + cb);
        float4 t1 = *(const float4*)(sT + (4*i4+1)*36 + cb);
        float4 t2 = *(const float4*)(sT + (4*i4+2)*36 + cb);
        float4 t3 = *(const float4*)(sT + (4*i4+3)*36 + cb);
        acc.x += av.x*t0.x + av.y*t1.x + av.z*t2.x + av.w*t3.x;
        acc.y += av.x*t0.y + av.y*t1.y + av.z*t2.y + av.w*t3.y;
        acc.z += av.x*t0.z + av.y*t1.z + av.z*t2.z + av.w*t3.z;
        acc.w += av.x*t0.w + av.y*t1.w + av.z*t2.w + av.w*t3.w;
    }
    *(float4*)(sS + r*36 + cb) = acc;
}

// ======================= ANCHOR: d=68 (Schur), K=100 (pad 104) ==============
__device__ __forceinline__ float gA(int r, int c, const float* sM, const float* sT,
                                    const float* sS, const float* sW, const float* sV,
                                    const float* sXi)
{
    if (c >= 100) return 0.f;
    if (r < 64){
        if (c < 64) return sM[r*68 + c];
        if (c < 92) return sT[r*36 + (c-64)];
        if (c < 96) return sT[r*36 + 28 + (c-92)] + sW[r*4 + (c-92)];
        return -sW[r*4 + (c-96)];
    }
    if (r < 92){ int i = r-64;
        if (c < 64) return sT[c*36 + i];
        if (c < 92) return sS[i*36 + (c-64)];
        if (c < 96) return sS[i*36 + 28 + (c-92)] + sV[i*4 + (c-92)];
        return -sV[i*4 + (c-96)];
    }
    if (r < 96){ int m = r-92, i = 28+m;
        if (c < 64) return sT[c*36 + i] + sW[c*4 + m];
        if (c < 92) return sS[i*36 + (c-64)] + sV[(c-64)*4 + m];
        if (c < 96){ int j = c-92;
            return sS[i*36 + 28 + j] + sV[i*4 + j] + sV[(28+j)*4 + m] + sXi[m*4 + j]; }
        { int j = c-96; return -sV[i*4 + j] - sXi[m*4 + j]; }
    }
    { int m = r-96;
        if (c < 64) return -sW[c*4 + m];
        if (c < 92) return -sV[(c-64)*4 + m];
        if (c < 96){ int j = c-92; return -sV[(28+j)*4 + m] - sXi[m*4 + j]; }
        { int j = c-96; return sXi[m*4 + j]; }
    }
}

__global__ void __launch_bounds__(TPB, 3)
anchor_kernel(const float* __restrict__ xr, const float* __restrict__ Ain,
              const float* __restrict__ bin)
{
    extern __shared__ float sm[];
    float* sA  = sm;             // 32*68
    float* sM  = sA  + 2176;     // 64*68
    float* sT  = sM  + 4352;     // 64*36
    float* sS  = sT  + 2304;     // 32*36
    float* sY  = sS  + 1152;     // 64*4
    float* sW  = sY  + 256;      // 64*4
    float* sU  = sW  + 256;      // 32*4
    float* sV  = sU  + 128;      // 32*4
    float* sXi = sV  + 128;      // 16
    float* sv  = sXi + 16;       // 2*104
    float* su0 = sv  + 208;      // 68
    float* sdx = su0 + 68;       // 68
    float* sxr = sdx + 68;       // 64
    float* bR  = sxr + 64;       // 128
    float* bC  = bR  + 128;      // 128
    float* bP  = bC  + 128;      // 2 + pad

    const int p = blockIdx.x;
    const int t = threadIdx.x;
    const float* Ap = Ain + (size_t)p * 2048;
    const float* bp = bin + (size_t)p * 32;

    for (int e = t; e < 2048; e += TPB) sA[(e>>6)*68 + (e&63)] = Ap[e];
    if (t < 64) sxr[t] = xr[(size_t)p*64 + t];
    if (t >= 64 && t < 72){ int q = t-64; sv[100 + (q&3) + (q>>2)*104] = 0.f; }
    __syncthreads();

    gj64_reg(sA, sM, 2.0f + SIGMA_, bR, bC, bP);
    gemmT(sM, sA, sT);
    __syncthreads();
    gemmS(sA, sT, sS);
    __syncthreads();

    if (t == 0){
        float X[4][4];
        for (int m = 0; m < 4; ++m)
            for (int j = 0; j < 4; ++j)
                X[m][j] = ((m==j) ? (4.0f+SIGMA_) : 0.f) - sS[(28+m)*36 + 28 + j];
        for (int k = 0; k < 4; ++k){
            float pinv = 1.0f / X[k][k];
            for (int j = 0; j < 4; ++j) if (j != k) X[k][j] *= pinv;
            X[k][k] = pinv;
            for (int i = 0; i < 4; ++i) if (i != k){
                float f = X[i][k];
                for (int j = 0; j < 4; ++j) if (j != k) X[i][j] -= f * X[k][j];
                X[i][k] = -f * pinv;
            }
        }
        for (int m = 0; m < 4; ++m)
            for (int j = 0; j < 4; ++j) sXi[m*4+j] = X[m][j];
    }
    __syncthreads();
    if (t < 64){
        float y[4];
#pragma unroll
        for (int m = 0; m < 4; ++m){ y[m] = -sT[t*36 + 28 + m]; sY[t*4+m] = y[m]; }
#pragma unroll
        for (int m = 0; m < 4; ++m){
            float a = 0.f;
#pragma unroll
            for (int j = 0; j < 4; ++j) a += y[j] * sXi[j*4+m];
            sW[t*4+m] = a;
        }
    } else if (t < 96){
        int r = t - 64;
        float u[4];
#pragma unroll
        for (int m = 0; m < 4; ++m){ u[m] = -sS[r*36 + 28 + m]; sU[r*4+m] = u[m]; }
#pragma unroll
        for (int m = 0; m < 4; ++m){
            float a = 0.f;
#pragma unroll
            for (int j = 0; j < 4; ++j) a += u[j] * sXi[j*4+m];
            sV[r*4+m] = a;
        }
    }
    __syncthreads();
    // rank-4 updates, float4-vectorized (dot4 of contiguous 4-vectors)
    {
        const float4* W4 = (const float4*)sW;
        const float4* Y4 = (const float4*)sY;
        const float4* U4 = (const float4*)sU;
        const float4* V4 = (const float4*)sV;
        for (int e = t; e < 4096; e += TPB){
            int i = e >> 6, j = e & 63;
            sM[i*68 + j] += dot4(W4[i], Y4[j]);
        }
        for (int e = t; e < 2048; e += TPB){
            int i = e >> 5, a0 = e & 31;
            sT[i*36 + a0] += dot4(W4[i], U4[a0]);
        }
        for (int e = t; e < 1024; e += TPB){
            int r = e >> 5, c = e & 31;
            sS[r*36 + c] += dot4(V4[r], U4[c]);
        }
    }
    __syncthreads();
    if (t < 64) su0[t] = dotA(sM, t, sxr);
    else if (t < 68){
        int m = t - 64; float a = 0.f;
        for (int j = 0; j < 64; ++j) a -= sW[j*4+m] * sxr[j];
        su0[64+m] = a;
    }
    __syncthreads();

    const int row = t >> 1, h = t & 1;
    const int wid = t >> 5;
    float lo = 0.f, hi = 0.f, cx0 = 0.f;
    if (t < 200){
        if (row < 64){ lo = 0.f; hi = INFINITY; cx0 = su0[row]; }
        else if (row < 92){ int i = row-64; lo = -INFINITY; hi = bp[i]; cx0 = dotA(sA, i, su0); }
        else if (row < 96){ int m = row-92; int i = 28+m;
            lo = -INFINITY; hi = bp[i]; cx0 = dotA(sA, i, su0) - su0[64+m]; }
        else { int m = row-96; lo = 0.f; hi = INFINITY; cx0 = su0[64+m]; }
    }
    unsigned long long G2[26];
    if (t < 200){
#pragma unroll
        for (int c2 = 0; c2 < 26; ++c2){
            float g0 = gA(row, h*52 + 2*c2,     sM, sT, sS, sW, sV, sXi);
            float g1 = gA(row, h*52 + 2*c2 + 1, sM, sT, sS, sW, sV, sXi);
            PACK2(G2[c2], g0, g1);
        }
    }
    __syncthreads();

    // ADMM loop: warps 0..6 only (224 threads, named barrier 1); warp 7 waits.
    if (wid < 7){
        const unsigned smask = (wid == 6) ? 0xFFu : 0xFFFFFFFFu;
        float z = fminf(fmaxf(0.f, lo), hi), y = 0.f;
        for (int it = 0; it < ITERS; ++it){
            float* vb = sv + (it & 1) * 104;
            if (t < 200 && h == 0) vb[row] = z - y;
            BARX(1, 224);
            if (t < 200){
                const ulonglong2* v2 = (const ulonglong2*)vb + h*13;
                unsigned long long a0 = 0ull, a1 = 0ull, a2 = 0ull, a3 = 0ull;
#pragma unroll
                for (int c = 0; c < 13; ++c){
                    ulonglong2 vv = v2[c];
                    if (c & 1){ FMA2(a2, G2[2*c], vv.x); FMA2(a3, G2[2*c+1], vv.y); }
                    else      { FMA2(a0, G2[2*c], vv.x); FMA2(a1, G2[2*c+1], vv.y); }
                }
                float x0, x1, x2, x3, x4, x5, x6, x7;
                UNPK2(x0, x1, a0); UNPK2(x2, x3, a1); UNPK2(x4, x5, a2); UNPK2(x6, x7, a3);
                float acc = ((x0+x1)+(x2+x3)) + ((x4+x5)+(x6+x7));
                acc += __shfl_xor_sync(smask, acc, 1);
                float Cx = cx0 + acc;
                float zn = fminf(fmaxf(Cx + y, lo), hi);
                y += Cx - zn; z = zn;
            }
        }
    }
    __syncthreads();

    const float* vl = sv + ((ITERS-1) & 1) * 104;
    if (t < 64){
        float a = vl[t];
        for (int r = 0; r < 28; ++r) a += sA[r*68 + t] * vl[64+r];
#pragma unroll
        for (int r = 28; r < 32; ++r) a += sA[r*68 + t] * vl[92 + (r-28)];
        sdx[t] = a;
    } else if (t < 68){
        int m = t - 64; sdx[64+m] = vl[96+m] - vl[92+m];
    }
    __syncthreads();
    if (t < 64){
        float a = su0[t] + dotA(sM, t, sdx);
#pragma unroll
        for (int m = 0; m < 4; ++m) a -= sW[t*4+m] * sdx[64+m];
        g_xfeas[(size_t)p*64 + t] = a;
    }
}

// ======================= LMO: d=64, K=96 ====================================
__global__ void __launch_bounds__(TPB, 4)
lmo_kernel(const float* __restrict__ Ain, const float* __restrict__ bin,
           const float* __restrict__ W1, const float* __restrict__ w2,
           float* __restrict__ out)
{
    extern __shared__ float sm[];
    float* sA  = sm;             // 32*68 (normalized)
    float* sM  = sA  + 2176;     // 64*68
    float* sT  = sM  + 4352;     // 64*36
    float* sS  = sT  + 2304;     // 32*36
    float* sv  = sS  + 1152;     // 2*96
    float* su0 = sv  + 192;      // 64
    float* sd  = su0 + 64;       // 64
    float* sx  = sd  + 64;       // 64
    float* shb = sx  + 64;       // 256
    float* sg  = shb + 256;      // 64
    float* srv = sg  + 64;       // 32
    float* bR  = srv + 32;       // 128
    float* bC  = bR  + 128;      // 128
    float* bP  = bC  + 128;      // 2 + pad

    const int p = blockIdx.x;
    const int t = threadIdx.x;
    const float* Ap = Ain + (size_t)p * 2048;
    const float* bp = bin + (size_t)p * 32;

    for (int e = t; e < 2048; e += TPB) sA[(e>>6)*68 + (e&63)] = Ap[e];
    if (t < 64) sx[t] = g_xfeas[(size_t)p*64 + t];
    __syncthreads();

    if (t < 32){
        float ss = 0.f;
        const float* Ar = sA + t*68;
        for (int i = 0; i < 64; ++i) ss += Ar[i]*Ar[i];
        srv[t] = 1.0f / fmaxf(sqrtf(ss), 1e-12f);
    }
    {
        float a = 0.f;
        for (int i = 0; i < 64; ++i) a += sx[i] * W1[i*256 + t];
        float hh = tanhf(a);
        shb[t] = (1.f - hh*hh) * w2[t];
    }
    __syncthreads();
    for (int e = t; e < 2048; e += TPB){
        int r = e >> 6;
        sA[r*68 + (e&63)] *= srv[r];
    }
    {
        int wd = t >> 5, lane = t & 31;
        for (int rr = 0; rr < 8; ++rr){
            int i = wd*8 + rr;
            const float* Wr = W1 + i*256;
            float a = 0.f;
#pragma unroll
            for (int k = 0; k < 8; ++k) a += Wr[k*32 + lane] * shb[k*32 + lane];
#pragma unroll
            for (int o = 16; o; o >>= 1) a += __shfl_xor_sync(0xFFFFFFFFu, a, o);
            if (lane == 0) sg[i] = a;
        }
    }
    __syncthreads();

    gj64_reg(sA, sM, 1.0f + EPSLMO_ + SIGMA_, bR, bC, bP);
    gemmT(sM, sA, sT);
    __syncthreads();
    gemmS(sA, sT, sS);
    if (t < 64) su0[t] = dotA(sM, t, sg);
    __syncthreads();

    const int row = t >> 1, h = t & 1;
    const int wid = t >> 5;
    float lo = 0.f, hi = 0.f, cx0 = 0.f;
    if (t < 192){
        if (row < 64){ lo = 0.f; hi = INFINITY; cx0 = su0[row]; }
        else { int a = row - 64; lo = -INFINITY; hi = bp[a] * srv[a]; cx0 = dotA(sA, a, su0); }
    }
    unsigned long long G2[24];
    if (t < 192){
#pragma unroll
        for (int c2 = 0; c2 < 24; ++c2){
            int c0 = h*48 + 2*c2, c1 = c0 + 1;
            float g0, g1;
            if (row < 64){
                g0 = (c0 < 64) ? sM[row*68 + c0] : sT[row*36 + (c0-64)];
                g1 = (c1 < 64) ? sM[row*68 + c1] : sT[row*36 + (c1-64)];
            } else {
                int a = row - 64;
                g0 = (c0 < 64) ? sT[c0*36 + a] : sS[a*36 + (c0-64)];
                g1 = (c1 < 64) ? sT[c1*36 + a] : sS[a*36 + (c1-64)];
            }
            PACK2(G2[c2], g0, g1);
        }
    }
    __syncthreads();

    // ADMM loop: warps 0..5 only (192 threads, named barrier 1); warps 6,7 wait.
    if (wid < 6){
        float z = fminf(fmaxf(0.f, lo), hi), y = 0.f;
        for (int it = 0; it < ITERS; ++it){
            float* vb = sv + (it & 1) * 96;
            if (h == 0) vb[row] = z - y;
            BARX(1, 192);
            const ulonglong2* v2 = (const ulonglong2*)vb + h*12;
            unsigned long long a0 = 0ull, a1 = 0ull, a2 = 0ull, a3 = 0ull;
#pragma unroll
            for (int c = 0; c < 12; ++c){
                ulonglong2 vv = v2[c];
                if (c & 1){ FMA2(a2, G2[2*c], vv.x); FMA2(a3, G2[2*c+1], vv.y); }
                else      { FMA2(a0, G2[2*c], vv.x); FMA2(a1, G2[2*c+1], vv.y); }
            }
            float x0, x1, x2, x3, x4, x5, x6, x7;
            UNPK2(x0, x1, a0); UNPK2(x2, x3, a1); UNPK2(x4, x5, a2); UNPK2(x6, x7, a3);
            float acc = ((x0+x1)+(x2+x3)) + ((x4+x5)+(x6+x7));
            acc += __shfl_xor_sync(0xFFFFFFFFu, acc, 1);
            float Cx = cx0 + acc;
            float zn = fminf(fmaxf(Cx + y, lo), hi);
            y += Cx - zn; z = zn;
        }
    }
    __syncthreads();

    const float* vl = sv + ((ITERS-1) & 1) * 96;
    if (t < 64){
        float a = vl[t];
        for (int r = 0; r < 32; ++r) a += sA[r*68 + t] * vl[64+r];
        sd[t] = a;
    }
    __syncthreads();
    if (t < 64){
        float c_sol = su0[t] + dotA(sM, t, sd);
        out[(size_t)p*64 + t] = 0.9f * sx[t] + 0.1f * c_sol;
    }
}

// ---------------------------------------------------------------------------
extern "C" void kernel_launch(void* const* d_in, const int* in_sizes, int n_in,
                              void* d_out, int out_size)
{
    const float* xr = (const float*)d_in[0];
    const float* A  = (const float*)d_in[1];
    const float* b  = (const float*)d_in[2];
    const float* W1 = (const float*)d_in[3];
    const float* w2 = (const float*)d_in[4];
    float* out = (float*)d_out;

    const int a_smem = (2176 + 4352 + 2304 + 1152 + 256 + 256 + 128 + 128 + 16
                        + 208 + 68 + 68 + 64 + 128 + 128 + 8) * (int)sizeof(float);
    const int l_smem = (2176 + 4352 + 2304 + 1152 + 192 + 64 + 64 + 64 + 256
                        + 64 + 32 + 128 + 128 + 8) * (int)sizeof(float);

    cudaFuncSetAttribute(anchor_kernel, cudaFuncAttributeMaxDynamicSharedMemorySize, a_smem);
    cudaFuncSetAttribute(lmo_kernel,    cudaFuncAttributeMaxDynamicSharedMemorySize, l_smem);

    anchor_kernel<<<NPROB, TPB, a_smem>>>(xr, A, b);
    lmo_kernel<<<NPROB, TPB, l_smem>>>(A, b, W1, w2, out);
}

// round 15
// speedup vs baseline: 1.0891x; 1.0042x over previous
#include <cuda_runtime.h>
#include <math.h>

#define NPROB 4096
#define TPB   256
#define ITERS 80
static constexpr float SIGMA_  = 1e-6f;
static constexpr float EPSLMO_ = 1e-4f;

__device__ float g_xfeas[NPROB * 64];

#define FMA2(d,a,b)  asm("fma.rn.f32x2 %0, %1, %2, %0;" : "+l"(d) : "l"(a), "l"(b))
#define ADD2(d,a,b)  asm("add.rn.f32x2 %0, %1, %2;" : "=l"(d) : "l"(a), "l"(b))
#define PACK2(d,x,y) asm("mov.b64 %0, {%1, %2};" : "=l"(d) : "f"(x), "f"(y))
#define UNPK2(x,y,v) asm("mov.b64 {%0, %1}, %2;" : "=f"(x), "=f"(y) : "l"(v))
#define BARX(id,n)   asm volatile("bar.sync %0, %1;" :: "r"(id), "r"(n) : "memory")

__device__ __forceinline__ float dot4(float4 a, float4 b){
    return a.x*b.x + a.y*b.y + a.z*b.z + a.w*b.w;
}
__device__ __forceinline__ float dotA(const float* sA, int i, const float* v){
    const float4* a4 = (const float4*)(sA + i*68);
    const float4* v4 = (const float4*)v;
    float s = 0.f;
#pragma unroll
    for (int q = 0; q < 16; ++q) s += dot4(a4[q], v4[q]);
    return s;
}

// ---------------------------------------------------------------------------
// Register-resident GJ inverse of M = diag*I + A^T A (64x64), result -> sM.
// Thread t: row gi = t&63, cols [j0, j0+16), j0 = (t>>6)*16, in R[16].
// ---------------------------------------------------------------------------
__device__ __forceinline__ void gj64_reg(const float* sA, float* sM, float diag,
                                         float* bufRow, float* bufCol, float* bufPinv)
{
    const int t  = threadIdx.x;
    const int gi = t & 63;
    const int cb = t >> 6;
    const int j0 = cb << 4;

    float R[16];
#pragma unroll
    for (int l = 0; l < 16; ++l) R[l] = 0.f;
    for (int r = 0; r < 32; ++r){
        float  ag = sA[r*68 + gi];
        float4 a0 = *(const float4*)(sA + r*68 + j0);
        float4 a1 = *(const float4*)(sA + r*68 + j0 + 4);
        float4 a2 = *(const float4*)(sA + r*68 + j0 + 8);
        float4 a3 = *(const float4*)(sA + r*68 + j0 + 12);
        R[0]+=ag*a0.x; R[1]+=ag*a0.y; R[2]+=ag*a0.z; R[3]+=ag*a0.w;
        R[4]+=ag*a1.x; R[5]+=ag*a1.y; R[6]+=ag*a1.z; R[7]+=ag*a1.w;
        R[8]+=ag*a2.x; R[9]+=ag*a2.y; R[10]+=ag*a2.z; R[11]+=ag*a2.w;
        R[12]+=ag*a3.x; R[13]+=ag*a3.y; R[14]+=ag*a3.z; R[15]+=ag*a3.w;
    }
    if ((gi >> 4) == cb){
#pragma unroll
        for (int l = 0; l < 16; ++l) if ((gi & 15) == l) R[l] += diag;
    }
    if (gi == 0){
        *(float4*)(bufRow + j0)      = make_float4(R[0],R[1],R[2],R[3]);
        *(float4*)(bufRow + j0 + 4)  = make_float4(R[4],R[5],R[6],R[7]);
        *(float4*)(bufRow + j0 + 8)  = make_float4(R[8],R[9],R[10],R[11]);
        *(float4*)(bufRow + j0 + 12) = make_float4(R[12],R[13],R[14],R[15]);
        if (cb == 0) bufPinv[0] = __frcp_rn(R[0]);
    }
    if (cb == 0) bufCol[gi] = R[0];
    __syncthreads();

    for (int ko = 0; ko < 4; ++ko){
#pragma unroll
        for (int ki = 0; ki < 16; ++ki){
            const int k = ko*16 + ki;
            const int b = ki & 1;
            float pinv = bufPinv[b];
            float pc   = bufCol[b*64 + gi];
            const bool isk = (gi == k);
            float fac = isk ? pinv : (-pc * pinv);
#pragma unroll
            for (int q = 0; q < 4; ++q){
                float4 p = *(const float4*)(bufRow + b*64 + j0 + 4*q);
                if (isk){
                    R[4*q+0] = p.x*fac; R[4*q+1] = p.y*fac;
                    R[4*q+2] = p.z*fac; R[4*q+3] = p.w*fac;
                } else {
                    R[4*q+0] += p.x*fac; R[4*q+1] += p.y*fac;
                    R[4*q+2] += p.z*fac; R[4*q+3] += p.w*fac;
                }
            }
            if (ko == cb) R[ki] = isk ? pinv : fac;
            if (k < 63){
                const int kn  = k + 1;
                const int bn  = kn & 1;
                const int kol = (ki == 15) ? (ko + 1) : ko;
                const int lnl = (ki + 1) & 15;
                if (gi == kn){
                    *(float4*)(bufRow + bn*64 + j0)      = make_float4(R[0],R[1],R[2],R[3]);
                    *(float4*)(bufRow + bn*64 + j0 + 4)  = make_float4(R[4],R[5],R[6],R[7]);
                    *(float4*)(bufRow + bn*64 + j0 + 8)  = make_float4(R[8],R[9],R[10],R[11]);
                    *(float4*)(bufRow + bn*64 + j0 + 12) = make_float4(R[12],R[13],R[14],R[15]);
                    if (kol == cb) bufPinv[bn] = __frcp_rn(R[lnl]);
                }
                if (kol == cb) bufCol[bn*64 + gi] = R[lnl];
            }
            __syncthreads();
        }
    }
    *(float4*)(sM + gi*68 + j0)      = make_float4(R[0],R[1],R[2],R[3]);
    *(float4*)(sM + gi*68 + j0 + 4)  = make_float4(R[4],R[5],R[6],R[7]);
    *(float4*)(sM + gi*68 + j0 + 8)  = make_float4(R[8],R[9],R[10],R[11]);
    *(float4*)(sM + gi*68 + j0 + 12) = make_float4(R[12],R[13],R[14],R[15]);
    __syncthreads();
}

// T (64x32, stride 36) = N * A^T
__device__ __forceinline__ void gemmT(const float* sM, const float* sA, float* sT)
{
    const int t  = threadIdx.x;
    const int i0 = (t >> 4) << 2;
    const int r0 = (t & 15) << 1;
    float acc[4][2] = {};
    for (int j = 0; j < 64; j += 4){
        float4 a0 = *(const float4*)(sA + r0*68     + j);
        float4 a1 = *(const float4*)(sA + (r0+1)*68 + j);
#pragma unroll
        for (int a = 0; a < 4; ++a){
            float4 nv = *(const float4*)(sM + (i0+a)*68 + j);
            acc[a][0] += dot4(nv, a0);
            acc[a][1] += dot4(nv, a1);
        }
    }
#pragma unroll
    for (int a = 0; a < 4; ++a){
        sT[(i0+a)*36 + r0]     = acc[a][0];
        sT[(i0+a)*36 + r0 + 1] = acc[a][1];
    }
}

// S (32x32, stride 36) = A * T  (A operand as broadcast float4)
__device__ __forceinline__ void gemmS(const float* sA, const float* sT, float* sS)
{
    const int t  = threadIdx.x;
    const int r  = t >> 3;
    const int cb = (t & 7) << 2;
    float4 acc = make_float4(0.f,0.f,0.f,0.f);
#pragma unroll
    for (int i4 = 0; i4 < 16; ++i4){
        float4 av = *(const float4*)(sA + r*68 + 4*i4);
        float4 t0 = *(const float4*)(sT + (4*i4+0)*36 + cb);
        float4 t1 = *(const float4*)(sT + (4*i4+1)*36 + cb);
        float4 t2 = *(const float4*)(sT + (4*i4+2)*36 + cb);
        float4 t3 = *(const float4*)(sT + (4*i4+3)*36 + cb);
        acc.x += av.x*t0.x + av.y*t1.x + av.z*t2.x + av.w*t3.x;
        acc.y += av.x*t0.y + av.y*t1.y + av.z*t2.y + av.w*t3.y;
        acc.z += av.x*t0.z + av.y*t1.z + av.z*t2.z + av.w*t3.z;
        acc.w += av.x*t0.w + av.y*t1.w + av.z*t2.w + av.w*t3.w;
    }
    *(float4*)(sS + r*36 + cb) = acc;
}

// ======================= ANCHOR: d=68 (Schur), K=100 (pad 104) ==============
__device__ __forceinline__ float gA(int r, int c, const float* sM, const float* sT,
                                    const float* sS, const float* sW, const float* sV,
                                    const float* sXi)
{
    if (c >= 100) return 0.f;
    if (r < 64){
        if (c < 64) return sM[r*68 + c];
        if (c < 92) return sT[r*36 + (c-64)];
        if (c < 96) return sT[r*36 + 28 + (c-92)] + sW[r*4 + (c-92)];
        return -sW[r*4 + (c-96)];
    }
    if (r < 92){ int i = r-64;
        if (c < 64) return sT[c*36 + i];
        if (c < 92) return sS[i*36 + (c-64)];
        if (c < 96) return sS[i*36 + 28 + (c-92)] + sV[i*4 + (c-92)];
        return -sV[i*4 + (c-96)];
    }
    if (r < 96){ int m = r-92, i = 28+m;
        if (c < 64) return sT[c*36 + i] + sW[c*4 + m];
        if (c < 92) return sS[i*36 + (c-64)] + sV[(c-64)*4 + m];
        if (c < 96){ int j = c-92;
            return sS[i*36 + 28 + j] + sV[i*4 + j] + sV[(28+j)*4 + m] + sXi[m*4 + j]; }
        { int j = c-96; return -sV[i*4 + j] - sXi[m*4 + j]; }
    }
    { int m = r-96;
        if (c < 64) return -sW[c*4 + m];
        if (c < 92) return -sV[(c-64)*4 + m];
        if (c < 96){ int j = c-92; return -sV[(28+j)*4 + m] - sXi[m*4 + j]; }
        { int j = c-96; return sXi[m*4 + j]; }
    }
}

__global__ void __launch_bounds__(TPB, 3)
anchor_kernel(const float* __restrict__ xr, const float* __restrict__ Ain,
              const float* __restrict__ bin)
{
    extern __shared__ float sm[];
    float* sA  = sm;             // 32*68
    float* sM  = sA  + 2176;     // 64*68
    float* sT  = sM  + 4352;     // 64*36
    float* sS  = sT  + 2304;     // 32*36
    float* sY  = sS  + 1152;     // 64*4
    float* sW  = sY  + 256;      // 64*4
    float* sU  = sW  + 256;      // 32*4
    float* sV  = sU  + 128;      // 32*4
    float* sXi = sV  + 128;      // 16
    float* sv  = sXi + 16;       // 2*104
    float* su0 = sv  + 208;      // 68
    float* sdx = su0 + 68;       // 68
    float* sxr = sdx + 68;       // 64
    float* bR  = sxr + 64;       // 128
    float* bC  = bR  + 128;      // 128
    float* bP  = bC  + 128;      // 2 + pad

    const int p = blockIdx.x;
    const int t = threadIdx.x;
    const float* Ap = Ain + (size_t)p * 2048;
    const float* bp = bin + (size_t)p * 32;

    for (int e = t; e < 2048; e += TPB) sA[(e>>6)*68 + (e&63)] = Ap[e];
    if (t < 64) sxr[t] = xr[(size_t)p*64 + t];
    if (t >= 64 && t < 72){ int q = t-64; sv[100 + (q&3) + (q>>2)*104] = 0.f; }
    __syncthreads();

    gj64_reg(sA, sM, 2.0f + SIGMA_, bR, bC, bP);
    gemmT(sM, sA, sT);
    __syncthreads();
    gemmS(sA, sT, sS);
    __syncthreads();

    if (t == 0){
        float X[4][4];
        for (int m = 0; m < 4; ++m)
            for (int j = 0; j < 4; ++j)
                X[m][j] = ((m==j) ? (4.0f+SIGMA_) : 0.f) - sS[(28+m)*36 + 28 + j];
        for (int k = 0; k < 4; ++k){
            float pinv = 1.0f / X[k][k];
            for (int j = 0; j < 4; ++j) if (j != k) X[k][j] *= pinv;
            X[k][k] = pinv;
            for (int i = 0; i < 4; ++i) if (i != k){
                float f = X[i][k];
                for (int j = 0; j < 4; ++j) if (j != k) X[i][j] -= f * X[k][j];
                X[i][k] = -f * pinv;
            }
        }
        for (int m = 0; m < 4; ++m)
            for (int j = 0; j < 4; ++j) sXi[m*4+j] = X[m][j];
    }
    __syncthreads();
    if (t < 64){
        float y[4];
#pragma unroll
        for (int m = 0; m < 4; ++m){ y[m] = -sT[t*36 + 28 + m]; sY[t*4+m] = y[m]; }
#pragma unroll
        for (int m = 0; m < 4; ++m){
            float a = 0.f;
#pragma unroll
            for (int j = 0; j < 4; ++j) a += y[j] * sXi[j*4+m];
            sW[t*4+m] = a;
        }
    } else if (t < 96){
        int r = t - 64;
        float u[4];
#pragma unroll
        for (int m = 0; m < 4; ++m){ u[m] = -sS[r*36 + 28 + m]; sU[r*4+m] = u[m]; }
#pragma unroll
        for (int m = 0; m < 4; ++m){
            float a = 0.f;
#pragma unroll
            for (int j = 0; j < 4; ++j) a += u[j] * sXi[j*4+m];
            sV[r*4+m] = a;
        }
    }
    __syncthreads();
    // rank-4 updates, float4-vectorized
    {
        const float4* W4 = (const float4*)sW;
        const float4* Y4 = (const float4*)sY;
        const float4* U4 = (const float4*)sU;
        const float4* V4 = (const float4*)sV;
        for (int e = t; e < 4096; e += TPB){
            int i = e >> 6, j = e & 63;
            sM[i*68 + j] += dot4(W4[i], Y4[j]);
        }
        for (int e = t; e < 2048; e += TPB){
            int i = e >> 5, a0 = e & 31;
            sT[i*36 + a0] += dot4(W4[i], U4[a0]);
        }
        for (int e = t; e < 1024; e += TPB){
            int r = e >> 5, c = e & 31;
            sS[r*36 + c] += dot4(V4[r], U4[c]);
        }
    }
    __syncthreads();
    if (t < 64) su0[t] = dotA(sM, t, sxr);
    else if (t < 68){
        int m = t - 64; float a = 0.f;
        for (int j = 0; j < 64; ++j) a -= sW[j*4+m] * sxr[j];
        su0[64+m] = a;
    }
    __syncthreads();

    const int row = t >> 1, h = t & 1;
    const int wid = t >> 5;
    float lo = 0.f, hi = 0.f, cx0 = 0.f;
    if (t < 200){
        if (row < 64){ lo = 0.f; hi = INFINITY; cx0 = su0[row]; }
        else if (row < 92){ int i = row-64; lo = -INFINITY; hi = bp[i]; cx0 = dotA(sA, i, su0); }
        else if (row < 96){ int m = row-92; int i = 28+m;
            lo = -INFINITY; hi = bp[i]; cx0 = dotA(sA, i, su0) - su0[64+m]; }
        else { int m = row-96; lo = 0.f; hi = INFINITY; cx0 = su0[64+m]; }
    }
    unsigned long long G2[26];
    if (t < 200){
#pragma unroll
        for (int c2 = 0; c2 < 26; ++c2){
            float g0 = gA(row, h*52 + 2*c2,     sM, sT, sS, sW, sV, sXi);
            float g1 = gA(row, h*52 + 2*c2 + 1, sM, sT, sS, sW, sV, sXi);
            PACK2(G2[c2], g0, g1);
        }
    }
    __syncthreads();

    // ADMM loop: warps 0..6 only (224 threads, named barrier 1); warp 7 waits.
    if (wid < 7){
        const unsigned smask = (wid == 6) ? 0xFFu : 0xFFFFFFFFu;
        float z = fminf(fmaxf(0.f, lo), hi), y = 0.f;
        for (int it = 0; it < ITERS; ++it){
            float* vb = sv + (it & 1) * 104;
            if (t < 200 && h == 0) vb[row] = z - y;
            BARX(1, 224);
            if (t < 200){
                const ulonglong2* v2 = (const ulonglong2*)vb + h*13;
                unsigned long long a0 = 0ull, a1 = 0ull, a2 = 0ull, a3 = 0ull;
#pragma unroll
                for (int c = 0; c < 13; ++c){
                    ulonglong2 vv = v2[c];
                    if (c & 1){ FMA2(a2, G2[2*c], vv.x); FMA2(a3, G2[2*c+1], vv.y); }
                    else      { FMA2(a0, G2[2*c], vv.x); FMA2(a1, G2[2*c+1], vv.y); }
                }
                unsigned long long s0, s1, s2;
                ADD2(s0, a0, a1); ADD2(s1, a2, a3); ADD2(s2, s0, s1);
                float xlo, xhi; UNPK2(xlo, xhi, s2);
                float acc = xlo + xhi;
                acc += __shfl_xor_sync(smask, acc, 1);
                float Cx = cx0 + acc;
                float zn = fminf(fmaxf(Cx + y, lo), hi);
                y += Cx - zn; z = zn;
            }
        }
    }
    __syncthreads();

    const float* vl = sv + ((ITERS-1) & 1) * 104;
    if (t < 64){
        float a = vl[t];
        for (int r = 0; r < 28; ++r) a += sA[r*68 + t] * vl[64+r];
#pragma unroll
        for (int r = 28; r < 32; ++r) a += sA[r*68 + t] * vl[92 + (r-28)];
        sdx[t] = a;
    } else if (t < 68){
        int m = t - 64; sdx[64+m] = vl[96+m] - vl[92+m];
    }
    __syncthreads();
    if (t < 64){
        float a = su0[t] + dotA(sM, t, sdx);
#pragma unroll
        for (int m = 0; m < 4; ++m) a -= sW[t*4+m] * sdx[64+m];
        g_xfeas[(size_t)p*64 + t] = a;
    }
}

// ======================= LMO: d=64, K=96 ====================================
__global__ void __launch_bounds__(TPB, 4)
lmo_kernel(const float* __restrict__ Ain, const float* __restrict__ bin,
           const float* __restrict__ W1, const float* __restrict__ w2,
           float* __restrict__ out)
{
    extern __shared__ float sm[];
    float* sA  = sm;             // 32*68 (normalized)
    float* sM  = sA  + 2176;     // 64*68
    float* sT  = sM  + 4352;     // 64*36
    float* sS  = sT  + 2304;     // 32*36
    float* sv  = sS  + 1152;     // 2*96
    float* su0 = sv  + 192;      // 64
    float* sd  = su0 + 64;       // 64
    float* sx  = sd  + 64;       // 64
    float* shb = sx  + 64;       // 256
    float* sg  = shb + 256;      // 64
    float* srv = sg  + 64;       // 32
    float* bR  = srv + 32;       // 128
    float* bC  = bR  + 128;      // 128
    float* bP  = bC  + 128;      // 2 + pad

    const int p = blockIdx.x;
    const int t = threadIdx.x;
    const float* Ap = Ain + (size_t)p * 2048;
    const float* bp = bin + (size_t)p * 32;

    for (int e = t; e < 2048; e += TPB) sA[(e>>6)*68 + (e&63)] = Ap[e];
    if (t < 64) sx[t] = g_xfeas[(size_t)p*64 + t];
    __syncthreads();

    if (t < 32){
        float ss = 0.f;
        const float* Ar = sA + t*68;
        for (int i = 0; i < 64; ++i) ss += Ar[i]*Ar[i];
        srv[t] = 1.0f / fmaxf(sqrtf(ss), 1e-12f);
    }
    {
        float a = 0.f;
        for (int i = 0; i < 64; ++i) a += sx[i] * W1[i*256 + t];
        float hh = tanhf(a);
        shb[t] = (1.f - hh*hh) * w2[t];
    }
    __syncthreads();
    for (int e = t; e < 2048; e += TPB){
        int r = e >> 6;
        sA[r*68 + (e&63)] *= srv[r];
    }
    {
        int wd = t >> 5, lane = t & 31;
        for (int rr = 0; rr < 8; ++rr){
            int i = wd*8 + rr;
            const float* Wr = W1 + i*256;
            float a = 0.f;
#pragma unroll
            for (int k = 0; k < 8; ++k) a += Wr[k*32 + lane] * shb[k*32 + lane];
#pragma unroll
            for (int o = 16; o; o >>= 1) a += __shfl_xor_sync(0xFFFFFFFFu, a, o);
            if (lane == 0) sg[i] = a;
        }
    }
    __syncthreads();

    gj64_reg(sA, sM, 1.0f + EPSLMO_ + SIGMA_, bR, bC, bP);
    gemmT(sM, sA, sT);
    __syncthreads();
    gemmS(sA, sT, sS);
    if (t < 64) su0[t] = dotA(sM, t, sg);
    __syncthreads();

    const int row = t >> 1, h = t & 1;
    const int wid = t >> 5;
    float lo = 0.f, hi = 0.f, cx0 = 0.f;
    if (t < 192){
        if (row < 64){ lo = 0.f; hi = INFINITY; cx0 = su0[row]; }
        else { int a = row - 64; lo = -INFINITY; hi = bp[a] * srv[a]; cx0 = dotA(sA, a, su0); }
    }
    unsigned long long G2[24];
    if (t < 192){
#pragma unroll
        for (int c2 = 0; c2 < 24; ++c2){
            int c0 = h*48 + 2*c2, c1 = c0 + 1;
            float g0, g1;
            if (row < 64){
                g0 = (c0 < 64) ? sM[row*68 + c0] : sT[row*36 + (c0-64)];
                g1 = (c1 < 64) ? sM[row*68 + c1] : sT[row*36 + (c1-64)];
            } else {
                int a = row - 64;
                g0 = (c0 < 64) ? sT[c0*36 + a] : sS[a*36 + (c0-64)];
                g1 = (c1 < 64) ? sT[c1*36 + a] : sS[a*36 + (c1-64)];
            }
            PACK2(G2[c2], g0, g1);
        }
    }
    __syncthreads();

    // ADMM loop: warps 0..5 only (192 threads, named barrier 1); warps 6,7 wait.
    if (wid < 6){
        float z = fminf(fmaxf(0.f, lo), hi), y = 0.f;
        for (int it = 0; it < ITERS; ++it){
            float* vb = sv + (it & 1) * 96;
            if (h == 0) vb[row] = z - y;
            BARX(1, 192);
            const ulonglong2* v2 = (const ulonglong2*)vb + h*12;
            unsigned long long a0 = 0ull, a1 = 0ull, a2 = 0ull, a3 = 0ull;
#pragma unroll
            for (int c = 0; c < 12; ++c){
                ulonglong2 vv = v2[c];
                if (c & 1){ FMA2(a2, G2[2*c], vv.x); FMA2(a3, G2[2*c+1], vv.y); }
                else      { FMA2(a0, G2[2*c], vv.x); FMA2(a1, G2[2*c+1], vv.y); }
            }
            unsigned long long s0, s1, s2;
            ADD2(s0, a0, a1); ADD2(s1, a2, a3); ADD2(s2, s0, s1);
            float xlo, xhi; UNPK2(xlo, xhi, s2);
            float acc = xlo + xhi;
            acc += __shfl_xor_sync(0xFFFFFFFFu, acc, 1);
            float Cx = cx0 + acc;
            float zn = fminf(fmaxf(Cx + y, lo), hi);
            y += Cx - zn; z = zn;
        }
    }
    __syncthreads();

    const float* vl = sv + ((ITERS-1) & 1) * 96;
    if (t < 64){
        float a = vl[t];
        for (int r = 0; r < 32; ++r) a += sA[r*68 + t] * vl[64+r];
        sd[t] = a;
    }
    __syncthreads();
    if (t < 64){
        float c_sol = su0[t] + dotA(sM, t, sd);
        out[(size_t)p*64 + t] = 0.9f * sx[t] + 0.1f * c_sol;
    }
}

// ---------------------------------------------------------------------------
extern "C" void kernel_launch(void* const* d_in, const int* in_sizes, int n_in,
                              void* d_out, int out_size)
{
    const float* xr = (const float*)d_in[0];
    const float* A  = (const float*)d_in[1];
    const float* b  = (const float*)d_in[2];
    const float* W1 = (const float*)d_in[3];
    const float* w2 = (const float*)d_in[4];
    float* out = (float*)d_out;

    const int a_smem = (2176 + 4352 + 2304 + 1152 + 256 + 256 + 128 + 128 + 16
                        + 208 + 68 + 68 + 64 + 128 + 128 + 8) * (int)sizeof(float);
    const int l_smem = (2176 + 4352 + 2304 + 1152 + 192 + 64 + 64 + 64 + 256
                        + 64 + 32 + 128 + 128 + 8) * (int)sizeof(float);

    cudaFuncSetAttribute(anchor_kernel, cudaFuncAttributeMaxDynamicSharedMemorySize, a_smem);
    cudaFuncSetAttribute(lmo_kernel,    cudaFuncAttributeMaxDynamicSharedMemorySize, l_smem);

    anchor_kernel<<<NPROB, TPB, a_smem>>>(xr, A, b);
    lmo_kernel<<<NPROB, TPB, l_smem>>>(A, b, W1, w2, out);
}

// round 16
// speedup vs baseline: 1.1192x; 1.0276x over previous
#include <cuda_runtime.h>
#include <math.h>

#define NPROB 4096
#define TPB   256
#define ITERS 80
static constexpr float SIGMA_  = 1e-6f;
static constexpr float EPSLMO_ = 1e-4f;

__device__ float g_xfeas[NPROB * 64];

#define FMA2(d,a,b)  asm("fma.rn.f32x2 %0, %1, %2, %0;" : "+l"(d) : "l"(a), "l"(b))
#define MUL2(d,a,b)  asm("mul.rn.f32x2 %0, %1, %2;" : "=l"(d) : "l"(a), "l"(b))
#define ADD2(d,a,b)  asm("add.rn.f32x2 %0, %1, %2;" : "=l"(d) : "l"(a), "l"(b))
#define PACK2(d,x,y) asm("mov.b64 %0, {%1, %2};" : "=l"(d) : "f"(x), "f"(y))
#define UNPK2(x,y,v) asm("mov.b64 {%0, %1}, %2;" : "=f"(x), "=f"(y) : "l"(v))
#define BARX(id,n)   asm volatile("bar.sync %0, %1;" :: "r"(id), "r"(n) : "memory")

__device__ __forceinline__ float dot4(float4 a, float4 b){
    return a.x*b.x + a.y*b.y + a.z*b.z + a.w*b.w;
}
__device__ __forceinline__ float dotA(const float* sA, int i, const float* v){
    const float4* a4 = (const float4*)(sA + i*68);
    const float4* v4 = (const float4*)v;
    float s = 0.f;
#pragma unroll
    for (int q = 0; q < 16; ++q) s += dot4(a4[q], v4[q]);
    return s;
}

// ---------------------------------------------------------------------------
// Register-resident GJ inverse of M = diag*I + A^T A (64x64), result -> sM.
// Thread t: row gi = t&63, cols [j0, j0+16) as 8 packed f32x2 pairs R2[8].
// All row updates via fma.rn.f32x2 (bit-identical to scalar FFMA pairs).
// ---------------------------------------------------------------------------
__device__ __forceinline__ void gj64_reg(const float* sA, float* sM, float diag,
                                         float* bufRow, float* bufCol, float* bufPinv)
{
    const int t  = threadIdx.x;
    const int gi = t & 63;
    const int cb = t >> 6;
    const int j0 = cb << 4;

    unsigned long long R2[8];
#pragma unroll
    for (int l = 0; l < 8; ++l) R2[l] = 0ull;

    // mform: M = diag*I + A^T A  (row gi, cols j0..j0+15)
    for (int r = 0; r < 32; ++r){
        float ag = sA[r*68 + gi];
        unsigned long long ag2; PACK2(ag2, ag, ag);
        const ulonglong2* ar = (const ulonglong2*)(sA + r*68 + j0);
        ulonglong2 c0 = ar[0], c1 = ar[1], c2 = ar[2], c3 = ar[3];
        FMA2(R2[0], ag2, c0.x); FMA2(R2[1], ag2, c0.y);
        FMA2(R2[2], ag2, c1.x); FMA2(R2[3], ag2, c1.y);
        FMA2(R2[4], ag2, c2.x); FMA2(R2[5], ag2, c2.y);
        FMA2(R2[6], ag2, c3.x); FMA2(R2[7], ag2, c3.y);
    }
    if ((gi >> 4) == cb){
#pragma unroll
        for (int l = 0; l < 8; ++l){
            if ((gi & 15) == 2*l || (gi & 15) == 2*l + 1){
                float lo, hi; UNPK2(lo, hi, R2[l]);
                if (gi & 1) hi += diag; else lo += diag;
                PACK2(R2[l], lo, hi);
            }
        }
    }
    // publish step 0
    if (gi == 0){
        ulonglong2* dst = (ulonglong2*)(bufRow + j0);
        dst[0] = make_ulonglong2(R2[0], R2[1]);
        dst[1] = make_ulonglong2(R2[2], R2[3]);
        dst[2] = make_ulonglong2(R2[4], R2[5]);
        dst[3] = make_ulonglong2(R2[6], R2[7]);
        if (cb == 0){
            float lo, hi; UNPK2(lo, hi, R2[0]);
            bufPinv[0] = __frcp_rn(lo);
        }
    }
    if (cb == 0){
        float lo, hi; UNPK2(lo, hi, R2[0]);
        bufCol[gi] = lo;
    }
    __syncthreads();

    for (int ko = 0; ko < 4; ++ko){
#pragma unroll
        for (int ki = 0; ki < 16; ++ki){
            const int k = ko*16 + ki;
            const int b = ki & 1;
            float pinv = bufPinv[b];
            float pc   = bufCol[b*64 + gi];
            const bool isk = (gi == k);
            float fac = isk ? pinv : (-pc * pinv);
            unsigned long long fac2; PACK2(fac2, fac, fac);
            const ulonglong2* pr = (const ulonglong2*)(bufRow + b*64 + j0);
            ulonglong2 p0 = pr[0], p1 = pr[1], p2 = pr[2], p3 = pr[3];
            if (isk){
                MUL2(R2[0], p0.x, fac2); MUL2(R2[1], p0.y, fac2);
                MUL2(R2[2], p1.x, fac2); MUL2(R2[3], p1.y, fac2);
                MUL2(R2[4], p2.x, fac2); MUL2(R2[5], p2.y, fac2);
                MUL2(R2[6], p3.x, fac2); MUL2(R2[7], p3.y, fac2);
            } else {
                FMA2(R2[0], fac2, p0.x); FMA2(R2[1], fac2, p0.y);
                FMA2(R2[2], fac2, p1.x); FMA2(R2[3], fac2, p1.y);
                FMA2(R2[4], fac2, p2.x); FMA2(R2[5], fac2, p2.y);
                FMA2(R2[6], fac2, p3.x); FMA2(R2[7], fac2, p3.y);
            }
            if (ko == cb){                 // R[ki] = fac (inverse column)
                float lo, hi; UNPK2(lo, hi, R2[ki >> 1]);
                if (ki & 1) hi = fac; else lo = fac;
                PACK2(R2[ki >> 1], lo, hi);
            }
            if (k < 63){
                const int kn  = k + 1;
                const int bn  = kn & 1;
                const int kol = (ki == 15) ? (ko + 1) : ko;
                const int lnl = (ki + 1) & 15;
                if (gi == kn){
                    ulonglong2* dst = (ulonglong2*)(bufRow + bn*64 + j0);
                    dst[0] = make_ulonglong2(R2[0], R2[1]);
                    dst[1] = make_ulonglong2(R2[2], R2[3]);
                    dst[2] = make_ulonglong2(R2[4], R2[5]);
                    dst[3] = make_ulonglong2(R2[6], R2[7]);
                    if (kol == cb){
                        float lo, hi; UNPK2(lo, hi, R2[lnl >> 1]);
                        bufPinv[bn] = __frcp_rn((lnl & 1) ? hi : lo);
                    }
                }
                if (kol == cb){
                    float lo, hi; UNPK2(lo, hi, R2[lnl >> 1]);
                    bufCol[bn*64 + gi] = (lnl & 1) ? hi : lo;
                }
            }
            __syncthreads();
        }
    }
    {
        ulonglong2* dst = (ulonglong2*)(sM + gi*68 + j0);
        dst[0] = make_ulonglong2(R2[0], R2[1]);
        dst[1] = make_ulonglong2(R2[2], R2[3]);
        dst[2] = make_ulonglong2(R2[4], R2[5]);
        dst[3] = make_ulonglong2(R2[6], R2[7]);
    }
    __syncthreads();
}

// T (64x32, stride 36) = N * A^T
__device__ __forceinline__ void gemmT(const float* sM, const float* sA, float* sT)
{
    const int t  = threadIdx.x;
    const int i0 = (t >> 4) << 2;
    const int r0 = (t & 15) << 1;
    float acc[4][2] = {};
    for (int j = 0; j < 64; j += 4){
        float4 a0 = *(const float4*)(sA + r0*68     + j);
        float4 a1 = *(const float4*)(sA + (r0+1)*68 + j);
#pragma unroll
        for (int a = 0; a < 4; ++a){
            float4 nv = *(const float4*)(sM + (i0+a)*68 + j);
            acc[a][0] += dot4(nv, a0);
            acc[a][1] += dot4(nv, a1);
        }
    }
#pragma unroll
    for (int a = 0; a < 4; ++a){
        sT[(i0+a)*36 + r0]     = acc[a][0];
        sT[(i0+a)*36 + r0 + 1] = acc[a][1];
    }
}

// S (32x32, stride 36) = A * T  (A operand as broadcast float4)
__device__ __forceinline__ void gemmS(const float* sA, const float* sT, float* sS)
{
    const int t  = threadIdx.x;
    const int r  = t >> 3;
    const int cb = (t & 7) << 2;
    float4 acc = make_float4(0.f,0.f,0.f,0.f);
#pragma unroll
    for (int i4 = 0; i4 < 16; ++i4){
        float4 av = *(const float4*)(sA + r*68 + 4*i4);
        float4 t0 = *(const float4*)(sT + (4*i4+0)*36 + cb);
        float4 t1 = *(const float4*)(sT + (4*i4+1)*36 + cb);
        float4 t2 = *(const float4*)(sT + (4*i4+2)*36 + cb);
        float4 t3 = *(const float4*)(sT + (4*i4+3)*36 + cb);
        acc.x += av.x*t0.x + av.y*t1.x + av.z*t2.x + av.w*t3.x;
        acc.y += av.x*t0.y + av.y*t1.y + av.z*t2.y + av.w*t3.y;
        acc.z += av.x*t0.z + av.y*t1.z + av.z*t2.z + av.w*t3.z;
        acc.w += av.x*t0.w + av.y*t1.w + av.z*t2.w + av.w*t3.w;
    }
    *(float4*)(sS + r*36 + cb) = acc;
}

// ======================= ANCHOR: d=68 (Schur), K=100 (pad 104) ==============
__device__ __forceinline__ float gA(int r, int c, const float* sM, const float* sT,
                                    const float* sS, const float* sW, const float* sV,
                                    const float* sXi)
{
    if (c >= 100) return 0.f;
    if (r < 64){
        if (c < 64) return sM[r*68 + c];
        if (c < 92) return sT[r*36 + (c-64)];
        if (c < 96) return sT[r*36 + 28 + (c-92)] + sW[r*4 + (c-92)];
        return -sW[r*4 + (c-96)];
    }
    if (r < 92){ int i = r-64;
        if (c < 64) return sT[c*36 + i];
        if (c < 92) return sS[i*36 + (c-64)];
        if (c < 96) return sS[i*36 + 28 + (c-92)] + sV[i*4 + (c-92)];
        return -sV[i*4 + (c-96)];
    }
    if (r < 96){ int m = r-92, i = 28+m;
        if (c < 64) return sT[c*36 + i] + sW[c*4 + m];
        if (c < 92) return sS[i*36 + (c-64)] + sV[(c-64)*4 + m];
        if (c < 96){ int j = c-92;
            return sS[i*36 + 28 + j] + sV[i*4 + j] + sV[(28+j)*4 + m] + sXi[m*4 + j]; }
        { int j = c-96; return -sV[i*4 + j] - sXi[m*4 + j]; }
    }
    { int m = r-96;
        if (c < 64) return -sW[c*4 + m];
        if (c < 92) return -sV[(c-64)*4 + m];
        if (c < 96){ int j = c-92; return -sV[(28+j)*4 + m] - sXi[m*4 + j]; }
        { int j = c-96; return sXi[m*4 + j]; }
    }
}

__global__ void __launch_bounds__(TPB, 3)
anchor_kernel(const float* __restrict__ xr, const float* __restrict__ Ain,
              const float* __restrict__ bin)
{
    extern __shared__ float sm[];
    float* sA  = sm;             // 32*68
    float* sM  = sA  + 2176;     // 64*68
    float* sT  = sM  + 4352;     // 64*36
    float* sS  = sT  + 2304;     // 32*36
    float* sY  = sS  + 1152;     // 64*4
    float* sW  = sY  + 256;      // 64*4
    float* sU  = sW  + 256;      // 32*4
    float* sV  = sU  + 128;      // 32*4
    float* sXi = sV  + 128;      // 16
    float* sv  = sXi + 16;       // 2*104
    float* su0 = sv  + 208;      // 68
    float* sdx = su0 + 68;       // 68
    float* sxr = sdx + 68;       // 64
    float* bR  = sxr + 64;       // 128
    float* bC  = bR  + 128;      // 128
    float* bP  = bC  + 128;      // 2 + pad

    const int p = blockIdx.x;
    const int t = threadIdx.x;
    const float* Ap = Ain + (size_t)p * 2048;
    const float* bp = bin + (size_t)p * 32;

    for (int e = t; e < 2048; e += TPB) sA[(e>>6)*68 + (e&63)] = Ap[e];
    if (t < 64) sxr[t] = xr[(size_t)p*64 + t];
    if (t >= 64 && t < 72){ int q = t-64; sv[100 + (q&3) + (q>>2)*104] = 0.f; }
    __syncthreads();

    gj64_reg(sA, sM, 2.0f + SIGMA_, bR, bC, bP);
    gemmT(sM, sA, sT);
    __syncthreads();
    gemmS(sA, sT, sS);
    __syncthreads();

    if (t == 0){
        float X[4][4];
        for (int m = 0; m < 4; ++m)
            for (int j = 0; j < 4; ++j)
                X[m][j] = ((m==j) ? (4.0f+SIGMA_) : 0.f) - sS[(28+m)*36 + 28 + j];
        for (int k = 0; k < 4; ++k){
            float pinv = 1.0f / X[k][k];
            for (int j = 0; j < 4; ++j) if (j != k) X[k][j] *= pinv;
            X[k][k] = pinv;
            for (int i = 0; i < 4; ++i) if (i != k){
                float f = X[i][k];
                for (int j = 0; j < 4; ++j) if (j != k) X[i][j] -= f * X[k][j];
                X[i][k] = -f * pinv;
            }
        }
        for (int m = 0; m < 4; ++m)
            for (int j = 0; j < 4; ++j) sXi[m*4+j] = X[m][j];
    }
    __syncthreads();
    if (t < 64){
        float y[4];
#pragma unroll
        for (int m = 0; m < 4; ++m){ y[m] = -sT[t*36 + 28 + m]; sY[t*4+m] = y[m]; }
#pragma unroll
        for (int m = 0; m < 4; ++m){
            float a = 0.f;
#pragma unroll
            for (int j = 0; j < 4; ++j) a += y[j] * sXi[j*4+m];
            sW[t*4+m] = a;
        }
    } else if (t < 96){
        int r = t - 64;
        float u[4];
#pragma unroll
        for (int m = 0; m < 4; ++m){ u[m] = -sS[r*36 + 28 + m]; sU[r*4+m] = u[m]; }
#pragma unroll
        for (int m = 0; m < 4; ++m){
            float a = 0.f;
#pragma unroll
            for (int j = 0; j < 4; ++j) a += u[j] * sXi[j*4+m];
            sV[r*4+m] = a;
        }
    }
    __syncthreads();
    // rank-4 updates, float4-vectorized
    {
        const float4* W4 = (const float4*)sW;
        const float4* Y4 = (const float4*)sY;
        const float4* U4 = (const float4*)sU;
        const float4* V4 = (const float4*)sV;
        for (int e = t; e < 4096; e += TPB){
            int i = e >> 6, j = e & 63;
            sM[i*68 + j] += dot4(W4[i], Y4[j]);
        }
        for (int e = t; e < 2048; e += TPB){
            int i = e >> 5, a0 = e & 31;
            sT[i*36 + a0] += dot4(W4[i], U4[a0]);
        }
        for (int e = t; e < 1024; e += TPB){
            int r = e >> 5, c = e & 31;
            sS[r*36 + c] += dot4(V4[r], U4[c]);
        }
    }
    __syncthreads();
    if (t < 64) su0[t] = dotA(sM, t, sxr);
    else if (t < 68){
        int m = t - 64; float a = 0.f;
        for (int j = 0; j < 64; ++j) a -= sW[j*4+m] * sxr[j];
        su0[64+m] = a;
    }
    __syncthreads();

    const int row = t >> 1, h = t & 1;
    const int wid = t >> 5;
    float lo = 0.f, hi = 0.f, cx0 = 0.f;
    if (t < 200){
        if (row < 64){ lo = 0.f; hi = INFINITY; cx0 = su0[row]; }
        else if (row < 92){ int i = row-64; lo = -INFINITY; hi = bp[i]; cx0 = dotA(sA, i, su0); }
        else if (row < 96){ int m = row-92; int i = 28+m;
            lo = -INFINITY; hi = bp[i]; cx0 = dotA(sA, i, su0) - su0[64+m]; }
        else { int m = row-96; lo = 0.f; hi = INFINITY; cx0 = su0[64+m]; }
    }
    unsigned long long G2[26];
    if (t < 200){
#pragma unroll
        for (int c2 = 0; c2 < 26; ++c2){
            float g0 = gA(row, h*52 + 2*c2,     sM, sT, sS, sW, sV, sXi);
            float g1 = gA(row, h*52 + 2*c2 + 1, sM, sT, sS, sW, sV, sXi);
            PACK2(G2[c2], g0, g1);
        }
    }
    __syncthreads();

    // ADMM loop: warps 0..6 only (224 threads, named barrier 1); warp 7 waits.
    if (wid < 7){
        const unsigned smask = (wid == 6) ? 0xFFu : 0xFFFFFFFFu;
        float z = fminf(fmaxf(0.f, lo), hi), y = 0.f;
        for (int it = 0; it < ITERS; ++it){
            float* vb = sv + (it & 1) * 104;
            if (t < 200 && h == 0) vb[row] = z - y;
            BARX(1, 224);
            if (t < 200){
                const ulonglong2* v2 = (const ulonglong2*)vb + h*13;
                unsigned long long a0 = 0ull, a1 = 0ull, a2 = 0ull, a3 = 0ull;
#pragma unroll
                for (int c = 0; c < 13; ++c){
                    ulonglong2 vv = v2[c];
                    if (c & 1){ FMA2(a2, G2[2*c], vv.x); FMA2(a3, G2[2*c+1], vv.y); }
                    else      { FMA2(a0, G2[2*c], vv.x); FMA2(a1, G2[2*c+1], vv.y); }
                }
                unsigned long long s0, s1, s2;
                ADD2(s0, a0, a1); ADD2(s1, a2, a3); ADD2(s2, s0, s1);
                float xlo, xhi; UNPK2(xlo, xhi, s2);
                float acc = xlo + xhi;
                acc += __shfl_xor_sync(smask, acc, 1);
                float Cx = cx0 + acc;
                float zn = fminf(fmaxf(Cx + y, lo), hi);
                y += Cx - zn; z = zn;
            }
        }
    }
    __syncthreads();

    const float* vl = sv + ((ITERS-1) & 1) * 104;
    if (t < 64){
        float a = vl[t];
        for (int r = 0; r < 28; ++r) a += sA[r*68 + t] * vl[64+r];
#pragma unroll
        for (int r = 28; r < 32; ++r) a += sA[r*68 + t] * vl[92 + (r-28)];
        sdx[t] = a;
    } else if (t < 68){
        int m = t - 64; sdx[64+m] = vl[96+m] - vl[92+m];
    }
    __syncthreads();
    if (t < 64){
        float a = su0[t] + dotA(sM, t, sdx);
#pragma unroll
        for (int m = 0; m < 4; ++m) a -= sW[t*4+m] * sdx[64+m];
        g_xfeas[(size_t)p*64 + t] = a;
    }
}

// ======================= LMO: d=64, K=96 ====================================
__global__ void __launch_bounds__(TPB, 4)
lmo_kernel(const float* __restrict__ Ain, const float* __restrict__ bin,
           const float* __restrict__ W1, const float* __restrict__ w2,
           float* __restrict__ out)
{
    extern __shared__ float sm[];
    float* sA  = sm;             // 32*68 (normalized)
    float* sM  = sA  + 2176;     // 64*68
    float* sT  = sM  + 4352;     // 64*36
    float* sS  = sT  + 2304;     // 32*36
    float* sv  = sS  + 1152;     // 2*96
    float* su0 = sv  + 192;      // 64
    float* sd  = su0 + 64;       // 64
    float* sx  = sd  + 64;       // 64
    float* shb = sx  + 64;       // 256
    float* sg  = shb + 256;      // 64
    float* srv = sg  + 64;       // 32
    float* bR  = srv + 32;       // 128
    float* bC  = bR  + 128;      // 128
    float* bP  = bC  + 128;      // 2 + pad

    const int p = blockIdx.x;
    const int t = threadIdx.x;
    const float* Ap = Ain + (size_t)p * 2048;
    const float* bp = bin + (size_t)p * 32;

    for (int e = t; e < 2048; e += TPB) sA[(e>>6)*68 + (e&63)] = Ap[e];
    if (t < 64) sx[t] = g_xfeas[(size_t)p*64 + t];
    __syncthreads();

    if (t < 32){
        float ss = 0.f;
        const float* Ar = sA + t*68;
        for (int i = 0; i < 64; ++i) ss += Ar[i]*Ar[i];
        srv[t] = 1.0f / fmaxf(sqrtf(ss), 1e-12f);
    }
    {
        float a = 0.f;
        for (int i = 0; i < 64; ++i) a += sx[i] * W1[i*256 + t];
        float hh = tanhf(a);
        shb[t] = (1.f - hh*hh) * w2[t];
    }
    __syncthreads();
    for (int e = t; e < 2048; e += TPB){
        int r = e >> 6;
        sA[r*68 + (e&63)] *= srv[r];
    }
    {
        int wd = t >> 5, lane = t & 31;
        for (int rr = 0; rr < 8; ++rr){
            int i = wd*8 + rr;
            const float* Wr = W1 + i*256;
            float a = 0.f;
#pragma unroll
            for (int k = 0; k < 8; ++k) a += Wr[k*32 + lane] * shb[k*32 + lane];
#pragma unroll
            for (int o = 16; o; o >>= 1) a += __shfl_xor_sync(0xFFFFFFFFu, a, o);
            if (lane == 0) sg[i] = a;
        }
    }
    __syncthreads();

    gj64_reg(sA, sM, 1.0f + EPSLMO_ + SIGMA_, bR, bC, bP);
    gemmT(sM, sA, sT);
    __syncthreads();
    gemmS(sA, sT, sS);
    if (t < 64) su0[t] = dotA(sM, t, sg);
    __syncthreads();

    const int row = t >> 1, h = t & 1;
    const int wid = t >> 5;
    float lo = 0.f, hi = 0.f, cx0 = 0.f;
    if (t < 192){
        if (row < 64){ lo = 0.f; hi = INFINITY; cx0 = su0[row]; }
        else { int a = row - 64; lo = -INFINITY; hi = bp[a] * srv[a]; cx0 = dotA(sA, a, su0); }
    }
    unsigned long long G2[24];
    if (t < 192){
#pragma unroll
        for (int c2 = 0; c2 < 24; ++c2){
            int c0 = h*48 + 2*c2, c1 = c0 + 1;
            float g0, g1;
            if (row < 64){
                g0 = (c0 < 64) ? sM[row*68 + c0] : sT[row*36 + (c0-64)];
                g1 = (c1 < 64) ? sM[row*68 + c1] : sT[row*36 + (c1-64)];
            } else {
                int a = row - 64;
                g0 = (c0 < 64) ? sT[c0*36 + a] : sS[a*36 + (c0-64)];
                g1 = (c1 < 64) ? sT[c1*36 + a] : sS[a*36 + (c1-64)];
            }
            PACK2(G2[c2], g0, g1);
        }
    }
    __syncthreads();

    // ADMM loop: warps 0..5 only (192 threads, named barrier 1); warps 6,7 wait.
    if (wid < 6){
        float z = fminf(fmaxf(0.f, lo), hi), y = 0.f;
        for (int it = 0; it < ITERS; ++it){
            float* vb = sv + (it & 1) * 96;
            if (h == 0) vb[row] = z - y;
            BARX(1, 192);
            const ulonglong2* v2 = (const ulonglong2*)vb + h*12;
            unsigned long long a0 = 0ull, a1 = 0ull, a2 = 0ull, a3 = 0ull;
#pragma unroll
            for (int c = 0; c < 12; ++c){
                ulonglong2 vv = v2[c];
                if (c & 1){ FMA2(a2, G2[2*c], vv.x); FMA2(a3, G2[2*c+1], vv.y); }
                else      { FMA2(a0, G2[2*c], vv.x); FMA2(a1, G2[2*c+1], vv.y); }
            }
            unsigned long long s0, s1, s2;
            ADD2(s0, a0, a1); ADD2(s1, a2, a3); ADD2(s2, s0, s1);
            float xlo, xhi; UNPK2(xlo, xhi, s2);
            float acc = xlo + xhi;
            acc += __shfl_xor_sync(0xFFFFFFFFu, acc, 1);
            float Cx = cx0 + acc;
            float zn = fminf(fmaxf(Cx + y, lo), hi);
            y += Cx - zn; z = zn;
        }
    }
    __syncthreads();

    const float* vl = sv + ((ITERS-1) & 1) * 96;
    if (t < 64){
        float a = vl[t];
        for (int r = 0; r < 32; ++r) a += sA[r*68 + t] * vl[64+r];
        sd[t] = a;
    }
    __syncthreads();
    if (t < 64){
        float c_sol = su0[t] + dotA(sM, t, sd);
        out[(size_t)p*64 + t] = 0.9f * sx[t] + 0.1f * c_sol;
    }
}

// ---------------------------------------------------------------------------
extern "C" void kernel_launch(void* const* d_in, const int* in_sizes, int n_in,
                              void* d_out, int out_size)
{
    const float* xr = (const float*)d_in[0];
    const float* A  = (const float*)d_in[1];
    const float* b  = (const float*)d_in[2];
    const float* W1 = (const float*)d_in[3];
    const float* w2 = (const float*)d_in[4];
    float* out = (float*)d_out;

    const int a_smem = (2176 + 4352 + 2304 + 1152 + 256 + 256 + 128 + 128 + 16
                        + 208 + 68 + 68 + 64 + 128 + 128 + 8) * (int)sizeof(float);
    const int l_smem = (2176 + 4352 + 2304 + 1152 + 192 + 64 + 64 + 64 + 256
                        + 64 + 32 + 128 + 128 + 8) * (int)sizeof(float);

    cudaFuncSetAttribute(anchor_kernel, cudaFuncAttributeMaxDynamicSharedMemorySize, a_smem);
    cudaFuncSetAttribute(lmo_kernel,    cudaFuncAttributeMaxDynamicSharedMemorySize, l_smem);

    anchor_kernel<<<NPROB, TPB, a_smem>>>(xr, A, b);
    lmo_kernel<<<NPROB, TPB, l_smem>>>(A, b, W1, w2, out);
}